// round 2
// baseline (speedup 1.0000x reference)
#include <cuda_runtime.h>
#include <math.h>
#include <stdint.h>

#define KMAX 64
#define BUF  16

// ---------------- device-global scratch (no allocations allowed) ----------------
__device__ float g_gt_cx[KMAX], g_gt_cy[KMAX], g_gt_w[KMAX], g_gt_h[KMAX];
__device__ int   g_gt_lvl[KMAX];
__device__ unsigned long long g_best[2][KMAX];   // packed (dd_bits<<32)|point_idx, min-reduced
__device__ int    g_pos_idx[2][KMAX];            // point index of positives
__device__ int    g_pos_gt[2][KMAX];             // assigned gt index
__device__ int    g_pos_cnt[2];
__device__ double g_cls_sum;                     // sum over n of (lse_n - cls[n,0])
__device__ double g_geo[4];                      // [loc_i, sc_i, loc_r, sc_r] raw sums

__device__ __forceinline__ float f_inf() { return __int_as_float(0x7f800000); }

// Non-FMA cross product: matches XLA's unfused mul/sub semantics exactly.
// Critical for the discrete hull-membership threshold (k==j term must be exact 0).
__device__ __forceinline__ float cross_nf(float ax, float ay, float bx, float by)
{
    return __fsub_rn(__fmul_rn(ax, by), __fmul_rn(ay, bx));
}

// ---------------- prep: per-gt center/size/level + reset accumulators ----------------
__global__ void k_prep(const float* __restrict__ gt, int K)
{
    int k = threadIdx.x;
    if (k == 0) { g_cls_sum = 0.0; g_pos_cnt[0] = 0; g_pos_cnt[1] = 0; }
    if (k < 4) g_geo[k] = 0.0;
    if (k < KMAX) { g_best[0][k] = ~0ull; g_best[1][k] = ~0ull; }
    if (k < K) {
        const float* r = gt + 8 * k;
        float xmn = fminf(fminf(r[0], r[2]), fminf(r[4], r[6]));
        float xmx = fmaxf(fmaxf(r[0], r[2]), fmaxf(r[4], r[6]));
        float ymn = fminf(fminf(r[1], r[3]), fminf(r[5], r[7]));
        float ymx = fmaxf(fmaxf(r[1], r[3]), fmaxf(r[5], r[7]));
        float w = fmaxf(__fsub_rn(xmx, xmn), 1e-6f);
        float h = fmaxf(__fsub_rn(ymx, ymn), 1e-6f);
        g_gt_cx[k] = __fmul_rn(__fadd_rn(xmn, xmx), 0.5f);
        g_gt_cy[k] = __fmul_rn(__fadd_rn(ymn, ymx), 0.5f);
        g_gt_w[k]  = w;
        g_gt_h[k]  = h;
        float lv = __fmul_rn(__fadd_rn(log2f(__fdiv_rn(w, 4.0f)),
                                       log2f(__fdiv_rn(h, 4.0f))), 0.5f);
        int lvl = (int)lv;                           // trunc toward zero (positive here)
        lvl = max(3, min(7, lvl));
        g_gt_lvl[k] = lvl;
    }
}

// ---------------- assign (both stages) + cls logsumexp partial sum ----------------
__global__ void k_assign(const float* __restrict__ rpi, const float* __restrict__ rpr,
                         const float* __restrict__ cls, const float* __restrict__ pstr,
                         int N, int K)
{
    __shared__ unsigned long long sb[2][KMAX];
    __shared__ float scx[KMAX], scy[KMAX], sw[KMAX], sh[KMAX];
    __shared__ int   slvl[KMAX];

    int t = threadIdx.x;
    for (int k = t; k < KMAX; k += blockDim.x) { sb[0][k] = ~0ull; sb[1][k] = ~0ull; }
    for (int k = t; k < K; k += blockDim.x) {
        scx[k] = g_gt_cx[k]; scy[k] = g_gt_cy[k];
        sw[k] = g_gt_w[k];   sh[k] = g_gt_h[k];
        slvl[k] = g_gt_lvl[k];
    }
    __syncthreads();

    int n = blockIdx.x * blockDim.x + t;
    double lterm = 0.0;
    if (n < N) {
        int lvl = 31 - __clz((int)pstr[n]);   // stride is an exact power of two
        float xi = rpi[n * 18 + 8], yi = rpi[n * 18 + 9];
        float xr = rpr[n * 18 + 8], yr = rpr[n * 18 + 9];
        unsigned un = (unsigned)n;
        for (int k = 0; k < K; k++) {
            if (slvl[k] != lvl) continue;
            // IEEE-exact path: matches XLA's precise div/sqrt, no FMA contraction
            float dxi = __fdiv_rn(__fsub_rn(xi, scx[k]), sw[k]);
            float dyi = __fdiv_rn(__fsub_rn(yi, scy[k]), sh[k]);
            float ddi = __fsqrt_rn(__fadd_rn(__fmul_rn(dxi, dxi), __fmul_rn(dyi, dyi)));
            unsigned long long ki = ((unsigned long long)__float_as_uint(ddi) << 32) | un;
            if (ki < sb[0][k]) atomicMin(&sb[0][k], ki);

            float dxr = __fdiv_rn(__fsub_rn(xr, scx[k]), sw[k]);
            float dyr = __fdiv_rn(__fsub_rn(yr, scy[k]), sh[k]);
            float ddr = __fsqrt_rn(__fadd_rn(__fmul_rn(dxr, dxr), __fmul_rn(dyr, dyr)));
            unsigned long long kr = ((unsigned long long)__float_as_uint(ddr) << 32) | un;
            if (kr < sb[1][k]) atomicMin(&sb[1][k], kr);
        }
        // logsumexp over 16 classes, minus class-0 logit (label correction added later)
        const float* c = cls + (size_t)n * 16;
        float v[16];
        #pragma unroll
        for (int j = 0; j < 16; j++) v[j] = c[j];
        float m = v[0];
        #pragma unroll
        for (int j = 1; j < 16; j++) m = fmaxf(m, v[j]);
        float s = 0.f;
        #pragma unroll
        for (int j = 0; j < 16; j++) s += expf(v[j] - m);
        lterm = (double)((m + logf(s)) - v[0]);
    }
    // warp-reduce the double partial, one atomic per warp
    for (int o = 16; o; o >>= 1) lterm += __shfl_down_sync(0xffffffffu, lterm, o);
    if ((t & 31) == 0) atomicAdd(&g_cls_sum, lterm);

    __syncthreads();
    for (int k = t; k < K; k += blockDim.x) {
        if (sb[0][k] != ~0ull) atomicMin(&g_best[0][k], sb[0][k]);
        if (sb[1][k] != ~0ull) atomicMin(&g_best[1][k], sb[1][k]);
    }
}

// ---------------- sequential scan replay (order matters, 64 steps, trivial) ----------------
__global__ void k_scan(int K)
{
    if (threadIdx.x != 0 || blockIdx.x != 0) return;
    for (int s = 0; s < 2; s++) {
        int   jl[KMAX], gl[KMAX];
        float dl[KMAX];
        int m = 0;
        for (int k = 0; k < K; k++) {
            unsigned long long key = g_best[s][k];
            if (key == ~0ull) continue;               // no candidate: md=inf, never wins
            float md = __uint_as_float((unsigned)(key >> 32));
            int j = (int)(unsigned)(key & 0xffffffffu);
            int p = -1;
            for (int q = 0; q < m; q++) if (jl[q] == j) { p = q; break; }
            if (p < 0) { jl[m] = j; gl[m] = k; dl[m] = md; m++; }
            else if (md < dl[p]) { gl[p] = k; dl[p] = md; }
        }
        g_pos_cnt[s] = m;
        for (int q = 0; q < m; q++) { g_pos_idx[s][q] = jl[q]; g_pos_gt[s][q] = gl[q]; }
    }
}

// ---------------- geometry helpers (replicate reference exactly in structure) ----------------
__device__ float shoelace16(const float2* V, int c)
{
    float s = 0.f;
    #pragma unroll
    for (int i = 0; i < BUF; i++) {
        if (i >= c) continue;
        int nxt = (i + 1 < c) ? i + 1 : 0;
        s = __fadd_rn(s, cross_nf(V[i].x, V[i].y, V[nxt].x, V[nxt].y));
    }
    return 0.5f * fabsf(s);
}

// convex hull per reference: edge(i,j) iff min_k cross(P[j]-P[i], P[k]-P[i]) >= -1e-6,
// hull[i] = any_j; vertices sorted by angle around hull centroid (stable; non-hull -> +inf)
__device__ int hull_sorted(const float2* P, int n, float2* V)
{
    bool hf[13];
    for (int i = 0; i < n; i++) {
        bool h = false;
        float pix = P[i].x, piy = P[i].y;
        for (int j = 0; j < n && !h; j++) {
            if (j == i) continue;
            float dx = __fsub_rn(P[j].x, pix), dy = __fsub_rn(P[j].y, piy);
            float mn = f_inf();
            for (int k = 0; k < n; k++) {
                // non-FMA: k==j term is exactly 0, matching XLA
                float cr = cross_nf(dx, dy, __fsub_rn(P[k].x, pix), __fsub_rn(P[k].y, piy));
                mn = fminf(mn, cr);
            }
            if (mn >= -1e-6f) h = true;
        }
        hf[i] = h;
    }
    int cnt = 0; float sx = 0.f, sy = 0.f;
    for (int i = 0; i < n; i++) if (hf[i]) { cnt++; sx = __fadd_rn(sx, P[i].x); sy = __fadd_rn(sy, P[i].y); }
    float cd = (float)(cnt > 0 ? cnt : 1);
    float cenx = __fdiv_rn(sx, cd), ceny = __fdiv_rn(sy, cd);
    float key[13]; int ord[13];
    for (int i = 0; i < n; i++) {
        key[i] = hf[i] ? atan2f(__fsub_rn(P[i].y, ceny), __fsub_rn(P[i].x, cenx)) : f_inf();
        ord[i] = i;
    }
    for (int i = 1; i < n; i++) {                    // stable insertion sort
        int oi = ord[i]; float ki = key[oi]; int j = i - 1;
        while (j >= 0 && key[ord[j]] > ki) { ord[j + 1] = ord[j]; j--; }
        ord[j + 1] = oi;
    }
    for (int i = 0; i < n; i++) V[i] = P[ord[i]];
    for (int i = n; i < BUF; i++) V[i] = make_float2(0.f, 0.f);
    return cnt;
}

__device__ void clip_poly(float2* V, int& c, float2 a, float2 b)
{
    float ex = __fsub_rn(b.x, a.x), ey = __fsub_rn(b.y, a.y);
    float2 out[BUF];
    int nc = 0;
    int cc = c;
    #pragma unroll
    for (int i = 0; i < BUF; i++) {
        bool active = i < cc;
        int nxt = (i + 1 < cc) ? i + 1 : 0;
        float2 cur = V[i], nx = V[nxt];
        // discrete in/out tests: non-FMA to match XLA sign behavior
        float s_cur = cross_nf(ex, ey, __fsub_rn(cur.x, a.x), __fsub_rn(cur.y, a.y));
        float s_nxt = cross_nf(ex, ey, __fsub_rn(nx.x,  a.x), __fsub_rn(nx.y,  a.y));
        bool in_cur = s_cur >= 0.f, in_nxt = s_nxt >= 0.f;
        float den = __fsub_rn(s_cur, s_nxt);
        float t = (fabsf(den) > 1e-9f) ? __fdiv_rn(s_cur, den) : 0.f;
        float2 ipt = make_float2(__fadd_rn(cur.x, __fmul_rn(t, __fsub_rn(nx.x, cur.x))),
                                 __fadd_rn(cur.y, __fmul_rn(t, __fsub_rn(nx.y, cur.y))));
        if (active && (in_cur != in_nxt)) { if (nc < BUF) out[nc] = ipt; nc++; }
        if (active && in_nxt)             { if (nc < BUF) out[nc] = nx;  nc++; }
    }
    #pragma unroll
    for (int i = 0; i < BUF; i++) V[i] = (i < nc) ? out[i] : make_float2(0.f, 0.f);
    c = nc;
}

__device__ void per_point(const float* g8, const float* p18, float& gl_out, float& oob_out)
{
    float2 gt4[4], P9[9];
    #pragma unroll
    for (int i = 0; i < 4; i++) gt4[i] = make_float2(g8[2 * i], g8[2 * i + 1]);
    #pragma unroll
    for (int i = 0; i < 9; i++) P9[i] = make_float2(p18[2 * i], p18[2 * i + 1]);

    // order gt corners CCW by angle around mean (stable sort)
    float cmx = (gt4[0].x + gt4[1].x + gt4[2].x + gt4[3].x) * 0.25f;
    float cmy = (gt4[0].y + gt4[1].y + gt4[2].y + gt4[3].y) * 0.25f;
    float ang[4]; int o4[4] = {0, 1, 2, 3};
    #pragma unroll
    for (int i = 0; i < 4; i++) ang[i] = atan2f(__fsub_rn(gt4[i].y, cmy), __fsub_rn(gt4[i].x, cmx));
    for (int i = 1; i < 4; i++) {
        int oi = o4[i]; float ki = ang[oi]; int j = i - 1;
        while (j >= 0 && ang[o4[j]] > ki) { o4[j + 1] = o4[j]; j--; }
        o4[j + 1] = oi;
    }
    float2 g[4];
    #pragma unroll
    for (int i = 0; i < 4; i++) g[i] = gt4[o4[i]];

    // prediction hull + area
    float2 V[BUF];
    int c = hull_sorted(P9, 9, V);
    float a_pred = shoelace16(V, c);

    // gt area
    float sgt = 0.f;
    #pragma unroll
    for (int i = 0; i < 4; i++) {
        int nx = (i + 1 < 4) ? i + 1 : 0;
        sgt = __fadd_rn(sgt, cross_nf(g[i].x, g[i].y, g[nx].x, g[nx].y));
    }
    float a_gt = 0.5f * fabsf(sgt);

    // clip hull by the 4 gt edges (Sutherland-Hodgman, exact reference semantics)
    for (int e = 0; e < 4; e++) clip_poly(V, c, g[e], g[(e + 1) & 3]);
    float a_int = shoelace16(V, c);

    float uni = __fsub_rn(__fadd_rn(a_pred, a_gt), a_int);
    float iou = __fdiv_rn(a_int, __fadd_rn(uni, 1e-16f));

    // hull of concat(gt4_original, p9)
    float2 H[13];
    #pragma unroll
    for (int i = 0; i < 4; i++) H[i] = gt4[i];
    #pragma unroll
    for (int i = 0; i < 9; i++) H[4 + i] = P9[i];
    float2 Vh[BUF];
    int ch = hull_sorted(H, 13, Vh);
    float a_hull = shoelace16(Vh, ch);

    float giou = __fsub_rn(iou, __fdiv_rn(__fsub_rn(a_hull, uni), __fadd_rn(a_hull, 1e-16f)));
    gl_out = __fsub_rn(1.0f, giou);

    // out-of-box penalty
    float acc = 0.f;
    #pragma unroll
    for (int p = 0; p < 9; p++) {
        float mx = -f_inf();
        #pragma unroll
        for (int e = 0; e < 4; e++) {
            float ex = __fsub_rn(g[(e + 1) & 3].x, g[e].x);
            float ey = __fsub_rn(g[(e + 1) & 3].y, g[e].y);
            float num = cross_nf(ex, ey, __fsub_rn(P9[p].x, g[e].x), __fsub_rn(P9[p].y, g[e].y));
            float s = __fdiv_rn(num,
                __fadd_rn(__fsqrt_rn(__fadd_rn(__fmul_rn(ex, ex), __fmul_rn(ey, ey))), 1e-9f));
            mx = fmaxf(mx, -s);
        }
        acc = __fadd_rn(acc, fmaxf(mx, 0.f));
    }
    oob_out = __fdiv_rn(acc, 9.0f);
}

// one task per block (lane 0); <=128 tasks total
__global__ void k_geom(const float* __restrict__ rpi, const float* __restrict__ rpr,
                       const float* __restrict__ gtb)
{
    if (threadIdx.x != 0) return;
    int b = blockIdx.x;
    int s = (b >= KMAX) ? 1 : 0;
    int m = b - s * KMAX;
    if (m >= g_pos_cnt[s]) return;
    const float* rp = s ? rpr : rpi;
    int j  = g_pos_idx[s][m];
    int gi = g_pos_gt[s][m];
    float gl, oob;
    per_point(gtb + 8 * gi, rp + (size_t)j * 18, gl, oob);
    atomicAdd(&g_geo[s * 2 + 0], (double)gl);
    atomicAdd(&g_geo[s * 2 + 1], (double)oob);
}

// ---------------- finalize: label correction + weighted combine ----------------
__global__ void k_final(const float* __restrict__ cls, const int* __restrict__ glab,
                        int N, float* __restrict__ out)
{
    if (threadIdx.x != 0 || blockIdx.x != 0) return;
    double corr = 0.0;
    int mr = g_pos_cnt[1];
    for (int q = 0; q < mr; q++) {
        int j   = g_pos_idx[1][q];
        int lab = glab[g_pos_gt[1][q]];
        corr += (double)cls[(size_t)j * 16 + 0] - (double)cls[(size_t)j * 16 + lab];
    }
    double cls_loss = (g_cls_sum + corr) / (double)N;
    double ni = (double)max(g_pos_cnt[0], 1);
    double nr = (double)max(g_pos_cnt[1], 1);
    double loss = cls_loss
                + 0.3  * (g_geo[0] / ni)
                + 1.0  * (g_geo[2] / nr)
                + 0.05 * (g_geo[1] / ni)
                + 0.1  * (g_geo[3] / nr);
    out[0] = (float)loss;
}

// ---------------- launch ----------------
extern "C" void kernel_launch(void* const* d_in, const int* in_sizes, int n_in,
                              void* d_out, int out_size)
{
    const float* rpi  = (const float*)d_in[0];
    const float* rpr  = (const float*)d_in[1];
    const float* cls  = (const float*)d_in[2];
    const float* pstr = (const float*)d_in[3];
    const float* gtb  = (const float*)d_in[4];
    const int*   glab = (const int*)d_in[5];
    float* out = (float*)d_out;

    int N = in_sizes[3];          // points_stride element count
    int K = in_sizes[5];          // gt_labels element count (=64)
    if (K > KMAX) K = KMAX;

    k_prep<<<1, 64>>>(gtb, K);
    k_assign<<<(N + 255) / 256, 256>>>(rpi, rpr, cls, pstr, N, K);
    k_scan<<<1, 32>>>(K);
    k_geom<<<2 * KMAX, 32>>>(rpi, rpr, gtb);
    k_final<<<1, 32>>>(cls, glab, N, out);
}

// round 3
// speedup vs baseline: 1.6894x; 1.6894x over previous
#include <cuda_runtime.h>
#include <math.h>
#include <stdint.h>

#define KMAX 64
#define BUF  16
#define NLVL 5          // levels 3..7

// ---------------- device-global scratch (no allocations allowed) ----------------
__device__ float g_gt_cx[KMAX], g_gt_cy[KMAX], g_gt_w[KMAX], g_gt_h[KMAX];
__device__ int   g_lvl_cnt[NLVL];
__device__ int   g_lvl_list[NLVL][KMAX];
__device__ unsigned long long g_best[2][KMAX];   // packed (dd_bits<<32)|point_idx, min-reduced
__device__ int    g_pos_idx[2][KMAX];            // point index of positives
__device__ int    g_pos_gt[2][KMAX];             // assigned gt index
__device__ int    g_pos_cnt[2];
__device__ double g_cls_sum;                     // sum over n of (lse_n - cls[n,0])
__device__ double g_geo[4];                      // [loc_i, sc_i, loc_r, sc_r] raw sums

__device__ __forceinline__ float f_inf() { return __int_as_float(0x7f800000); }

// Non-FMA cross product: matches XLA's unfused mul/sub semantics exactly.
__device__ __forceinline__ float cross_nf(float ax, float ay, float bx, float by)
{
    return __fsub_rn(__fmul_rn(ax, by), __fmul_rn(ay, bx));
}

// ---------------- prep: per-gt center/size/level buckets + reset accumulators ----------------
__global__ void k_prep(const float* __restrict__ gt, int K)
{
    __shared__ int s_lvl[KMAX];
    int k = threadIdx.x;
    if (k == 0) { g_cls_sum = 0.0; g_pos_cnt[0] = 0; g_pos_cnt[1] = 0; }
    if (k < 4) g_geo[k] = 0.0;
    if (k < KMAX) { g_best[0][k] = ~0ull; g_best[1][k] = ~0ull; }
    if (k < K) {
        const float* r = gt + 8 * k;
        float xmn = fminf(fminf(r[0], r[2]), fminf(r[4], r[6]));
        float xmx = fmaxf(fmaxf(r[0], r[2]), fmaxf(r[4], r[6]));
        float ymn = fminf(fminf(r[1], r[3]), fminf(r[5], r[7]));
        float ymx = fmaxf(fmaxf(r[1], r[3]), fmaxf(r[5], r[7]));
        float w = fmaxf(__fsub_rn(xmx, xmn), 1e-6f);
        float h = fmaxf(__fsub_rn(ymx, ymn), 1e-6f);
        g_gt_cx[k] = __fmul_rn(__fadd_rn(xmn, xmx), 0.5f);
        g_gt_cy[k] = __fmul_rn(__fadd_rn(ymn, ymx), 0.5f);
        g_gt_w[k]  = w;
        g_gt_h[k]  = h;
        float lv = __fmul_rn(__fadd_rn(log2f(__fdiv_rn(w, 4.0f)),
                                       log2f(__fdiv_rn(h, 4.0f))), 0.5f);
        int lvl = (int)lv;                           // trunc toward zero (positive here)
        lvl = max(3, min(7, lvl));
        s_lvl[k] = lvl;
    }
    __syncthreads();
    if (k == 0) {                                    // serial bucket build, ascending k
        int cnt[NLVL];
        #pragma unroll
        for (int l = 0; l < NLVL; l++) cnt[l] = 0;
        for (int q = 0; q < K; q++) {
            int li = s_lvl[q] - 3;
            g_lvl_list[li][cnt[li]++] = q;
        }
        #pragma unroll
        for (int l = 0; l < NLVL; l++) g_lvl_cnt[l] = cnt[l];
    }
}

// ---------------- assign (both stages, level-bucketed) + cls logsumexp ----------------
__global__ void k_assign(const float* __restrict__ rpi, const float* __restrict__ rpr,
                         const float* __restrict__ cls, const float* __restrict__ pstr,
                         int N, int K)
{
    __shared__ unsigned long long sb[2][KMAX];
    __shared__ float scx[KMAX], scy[KMAX], sw[KMAX], sh[KMAX];
    __shared__ int   slist[NLVL][KMAX];
    __shared__ int   scnt[NLVL];

    int t = threadIdx.x;
    for (int k = t; k < KMAX; k += blockDim.x) { sb[0][k] = ~0ull; sb[1][k] = ~0ull; }
    for (int k = t; k < K; k += blockDim.x) {
        scx[k] = g_gt_cx[k]; scy[k] = g_gt_cy[k];
        sw[k]  = g_gt_w[k];  sh[k]  = g_gt_h[k];
    }
    if (t < NLVL) scnt[t] = g_lvl_cnt[t];
    for (int q = t; q < NLVL * KMAX; q += blockDim.x)
        slist[q / KMAX][q % KMAX] = g_lvl_list[q / KMAX][q % KMAX];
    __syncthreads();

    int n = blockIdx.x * blockDim.x + t;
    double lterm = 0.0;
    if (n < N) {
        int li = (31 - __clz((int)pstr[n])) - 3;      // stride is an exact power of two
        float2 pi = __ldg((const float2*)(rpi + (size_t)n * 18 + 8));
        float2 pr = __ldg((const float2*)(rpr + (size_t)n * 18 + 8));
        unsigned un = (unsigned)n;
        int cnt = scnt[li];
        for (int m = 0; m < cnt; m++) {
            int k = slist[li][m];
            // IEEE-exact path: matches XLA's precise div/sqrt, no FMA contraction
            float dxi = __fdiv_rn(__fsub_rn(pi.x, scx[k]), sw[k]);
            float dyi = __fdiv_rn(__fsub_rn(pi.y, scy[k]), sh[k]);
            float ddi = __fsqrt_rn(__fadd_rn(__fmul_rn(dxi, dxi), __fmul_rn(dyi, dyi)));
            unsigned long long ki = ((unsigned long long)__float_as_uint(ddi) << 32) | un;
            if (ki < sb[0][k]) atomicMin(&sb[0][k], ki);

            float dxr = __fdiv_rn(__fsub_rn(pr.x, scx[k]), sw[k]);
            float dyr = __fdiv_rn(__fsub_rn(pr.y, scy[k]), sh[k]);
            float ddr = __fsqrt_rn(__fadd_rn(__fmul_rn(dxr, dxr), __fmul_rn(dyr, dyr)));
            unsigned long long kr = ((unsigned long long)__float_as_uint(ddr) << 32) | un;
            if (kr < sb[1][k]) atomicMin(&sb[1][k], kr);
        }
        // logsumexp over 16 classes, minus class-0 logit (label correction added later)
        const float4* c4 = (const float4*)(cls + (size_t)n * 16);
        float v[16];
        #pragma unroll
        for (int j = 0; j < 4; j++) {
            float4 f = __ldg(c4 + j);
            v[4 * j] = f.x; v[4 * j + 1] = f.y; v[4 * j + 2] = f.z; v[4 * j + 3] = f.w;
        }
        float m = v[0];
        #pragma unroll
        for (int j = 1; j < 16; j++) m = fmaxf(m, v[j]);
        float s = 0.f;
        #pragma unroll
        for (int j = 0; j < 16; j++) s += expf(v[j] - m);
        lterm = (double)((m + logf(s)) - v[0]);
    }
    // warp-reduce the double partial, one atomic per warp
    for (int o = 16; o; o >>= 1) lterm += __shfl_down_sync(0xffffffffu, lterm, o);
    if ((t & 31) == 0) atomicAdd(&g_cls_sum, lterm);

    __syncthreads();
    for (int k = t; k < K; k += blockDim.x) {
        if (sb[0][k] != ~0ull) atomicMin(&g_best[0][k], sb[0][k]);
        if (sb[1][k] != ~0ull) atomicMin(&g_best[1][k], sb[1][k]);
    }
}

// ---------------- sequential scan replay (order matters, 64 steps, trivial) ----------------
__global__ void k_scan(int K)
{
    if (threadIdx.x != 0 || blockIdx.x != 0) return;
    for (int s = 0; s < 2; s++) {
        int   jl[KMAX], gl[KMAX];
        float dl[KMAX];
        int m = 0;
        for (int k = 0; k < K; k++) {
            unsigned long long key = g_best[s][k];
            if (key == ~0ull) continue;               // no candidate: md=inf, never wins
            float md = __uint_as_float((unsigned)(key >> 32));
            int j = (int)(unsigned)(key & 0xffffffffu);
            int p = -1;
            for (int q = 0; q < m; q++) if (jl[q] == j) { p = q; break; }
            if (p < 0) { jl[m] = j; gl[m] = k; dl[m] = md; m++; }
            else if (md < dl[p]) { gl[p] = k; dl[p] = md; }
        }
        g_pos_cnt[s] = m;
        for (int q = 0; q < m; q++) { g_pos_idx[s][q] = jl[q]; g_pos_gt[s][q] = gl[q]; }
    }
}

// ---------------- geometry ----------------
__device__ float shoelace16(const float2* V, int c)
{
    float s = 0.f;
    #pragma unroll
    for (int i = 0; i < BUF; i++) {
        if (i >= c) continue;
        int nxt = (i + 1 < c) ? i + 1 : 0;
        s = __fadd_rn(s, cross_nf(V[i].x, V[i].y, V[nxt].x, V[nxt].y));
    }
    return 0.5f * fabsf(s);
}

// warp-parallel convex hull, reference semantics:
// edge(i,j) iff min_k cross(P[j]-P[i], P[k]-P[i]) >= -1e-6 (non-FMA, k==j term exact 0);
// hull[i] = any_j; vertices stably sorted by angle around hull centroid (non-hull -> +inf).
// sP: shared points [n]; skey: shared scratch [n]; sV: shared output [BUF].
__device__ int hull_block_sorted(const float2* sP, int n, float* skey, float2* sV, int lane)
{
    bool h = false;
    if (lane < n) {
        float pix = sP[lane].x, piy = sP[lane].y;
        for (int j = 0; j < n && !h; j++) {
            if (j == lane) continue;
            float dx = __fsub_rn(sP[j].x, pix), dy = __fsub_rn(sP[j].y, piy);
            float mn = f_inf();
            for (int k = 0; k < n; k++) {
                float cr = cross_nf(dx, dy, __fsub_rn(sP[k].x, pix), __fsub_rn(sP[k].y, piy));
                mn = fminf(mn, cr);            // min: exactly order-independent here
            }
            if (mn >= -1e-6f) h = true;
        }
    }
    unsigned mask = __ballot_sync(0xffffffffu, h);
    int cnt = __popc(mask);
    // centroid: serial ascending i on every lane (matches reference sum order)
    float sx = 0.f, sy = 0.f;
    for (int i = 0; i < n; i++)
        if ((mask >> i) & 1) { sx = __fadd_rn(sx, sP[i].x); sy = __fadd_rn(sy, sP[i].y); }
    float cd = (float)(cnt > 0 ? cnt : 1);
    float cenx = __fdiv_rn(sx, cd), ceny = __fdiv_rn(sy, cd);
    if (lane < n)
        skey[lane] = h ? atan2f(__fsub_rn(sP[lane].y, ceny), __fsub_rn(sP[lane].x, cenx))
                       : f_inf();
    __syncwarp();
    if (lane == 0) {
        int ord[13];
        for (int i = 0; i < n; i++) ord[i] = i;
        for (int i = 1; i < n; i++) {                 // stable insertion sort
            int oi = ord[i]; float ki = skey[oi]; int j = i - 1;
            while (j >= 0 && skey[ord[j]] > ki) { ord[j + 1] = ord[j]; j--; }
            ord[j + 1] = oi;
        }
        for (int i = 0; i < n; i++) sV[i] = sP[ord[i]];
        for (int i = n; i < BUF; i++) sV[i] = make_float2(0.f, 0.f);
    }
    __syncwarp();
    return cnt;
}

__device__ void clip_poly(float2* V, int& c, float2 a, float2 b)
{
    float ex = __fsub_rn(b.x, a.x), ey = __fsub_rn(b.y, a.y);
    float2 out[BUF];
    int nc = 0;
    int cc = c;
    #pragma unroll
    for (int i = 0; i < BUF; i++) {
        bool active = i < cc;
        int nxt = (i + 1 < cc) ? i + 1 : 0;
        float2 cur = V[i], nx = V[nxt];
        float s_cur = cross_nf(ex, ey, __fsub_rn(cur.x, a.x), __fsub_rn(cur.y, a.y));
        float s_nxt = cross_nf(ex, ey, __fsub_rn(nx.x,  a.x), __fsub_rn(nx.y,  a.y));
        bool in_cur = s_cur >= 0.f, in_nxt = s_nxt >= 0.f;
        float den = __fsub_rn(s_cur, s_nxt);
        float t = (fabsf(den) > 1e-9f) ? __fdiv_rn(s_cur, den) : 0.f;
        float2 ipt = make_float2(__fadd_rn(cur.x, __fmul_rn(t, __fsub_rn(nx.x, cur.x))),
                                 __fadd_rn(cur.y, __fmul_rn(t, __fsub_rn(nx.y, cur.y))));
        if (active && (in_cur != in_nxt)) { if (nc < BUF) out[nc] = ipt; nc++; }
        if (active && in_nxt)             { if (nc < BUF) out[nc] = nx;  nc++; }
    }
    #pragma unroll
    for (int i = 0; i < BUF; i++) V[i] = (i < nc) ? out[i] : make_float2(0.f, 0.f);
    c = nc;
}

// one task per block (warp of 32); <=128 tasks total
__global__ void k_geom(const float* __restrict__ rpi, const float* __restrict__ rpr,
                       const float* __restrict__ gtb)
{
    __shared__ float2 sPts[13];
    __shared__ float  sKey[13];
    __shared__ float2 sV[BUF];
    __shared__ float2 sGT[4];     // raw gt corners
    __shared__ float2 sG[4];      // CCW-ordered gt corners
    __shared__ float2 sP9[9];

    int lane = threadIdx.x;
    int b = blockIdx.x;
    int s = (b >= KMAX) ? 1 : 0;
    int m = b - s * KMAX;
    if (m >= g_pos_cnt[s]) return;
    const float* rp = s ? rpr : rpi;
    int j  = g_pos_idx[s][m];
    int gi = g_pos_gt[s][m];
    const float* g8  = gtb + 8 * gi;
    const float* p18 = rp + (size_t)j * 18;

    if (lane < 4) sGT[lane] = make_float2(g8[2 * lane], g8[2 * lane + 1]);
    if (lane < 9) sP9[lane] = make_float2(p18[2 * lane], p18[2 * lane + 1]);
    __syncwarp();

    // order gt corners CCW by angle around mean (lane 0, stable sort)
    if (lane == 0) {
        float cmx = (sGT[0].x + sGT[1].x + sGT[2].x + sGT[3].x) * 0.25f;
        float cmy = (sGT[0].y + sGT[1].y + sGT[2].y + sGT[3].y) * 0.25f;
        float ang[4]; int o4[4] = {0, 1, 2, 3};
        #pragma unroll
        for (int i = 0; i < 4; i++)
            ang[i] = atan2f(__fsub_rn(sGT[i].y, cmy), __fsub_rn(sGT[i].x, cmx));
        for (int i = 1; i < 4; i++) {
            int oi = o4[i]; float ki = ang[oi]; int jj = i - 1;
            while (jj >= 0 && ang[o4[jj]] > ki) { o4[jj + 1] = o4[jj]; jj--; }
            o4[jj + 1] = oi;
        }
        #pragma unroll
        for (int i = 0; i < 4; i++) sG[i] = sGT[o4[i]];
    }

    // prediction hull (9 points, warp-parallel membership)
    if (lane < 9) sPts[lane] = sP9[lane];
    __syncwarp();
    int c = hull_block_sorted(sPts, 9, sKey, sV, lane);

    float gl = 0.f, oob = 0.f;
    float a_pred = 0.f, a_gt = 0.f, a_int = 0.f;
    if (lane == 0) {
        float2 V[BUF];
        #pragma unroll
        for (int i = 0; i < BUF; i++) V[i] = sV[i];
        a_pred = shoelace16(V, c);

        float sgt = 0.f;
        #pragma unroll
        for (int i = 0; i < 4; i++) {
            int nx = (i + 1 < 4) ? i + 1 : 0;
            sgt = __fadd_rn(sgt, cross_nf(sG[i].x, sG[i].y, sG[nx].x, sG[nx].y));
        }
        a_gt = 0.5f * fabsf(sgt);

        int cc = c;
        for (int e = 0; e < 4; e++) clip_poly(V, cc, sG[e], sG[(e + 1) & 3]);
        a_int = shoelace16(V, cc);
    }

    // hull of concat(gt4_original, p9): 13 points, warp-parallel
    if (lane < 4)  sPts[lane] = sGT[lane];
    if (lane >= 4 && lane < 13) sPts[lane] = sP9[lane - 4];
    __syncwarp();
    int ch = hull_block_sorted(sPts, 13, sKey, sV, lane);

    if (lane == 0) {
        float a_hull = shoelace16(sV, ch);
        float uni = __fsub_rn(__fadd_rn(a_pred, a_gt), a_int);
        float iou = __fdiv_rn(a_int, __fadd_rn(uni, 1e-16f));
        float giou = __fsub_rn(iou, __fdiv_rn(__fsub_rn(a_hull, uni),
                                              __fadd_rn(a_hull, 1e-16f)));
        gl = __fsub_rn(1.0f, giou);

        // out-of-box penalty (serial: matches reference reduce order)
        float acc = 0.f;
        #pragma unroll
        for (int p = 0; p < 9; p++) {
            float mx = -f_inf();
            #pragma unroll
            for (int e = 0; e < 4; e++) {
                float ex = __fsub_rn(sG[(e + 1) & 3].x, sG[e].x);
                float ey = __fsub_rn(sG[(e + 1) & 3].y, sG[e].y);
                float num = cross_nf(ex, ey, __fsub_rn(sP9[p].x, sG[e].x),
                                             __fsub_rn(sP9[p].y, sG[e].y));
                float sv = __fdiv_rn(num,
                    __fadd_rn(__fsqrt_rn(__fadd_rn(__fmul_rn(ex, ex), __fmul_rn(ey, ey))),
                              1e-9f));
                mx = fmaxf(mx, -sv);
            }
            acc = __fadd_rn(acc, fmaxf(mx, 0.f));
        }
        oob = __fdiv_rn(acc, 9.0f);

        atomicAdd(&g_geo[s * 2 + 0], (double)gl);
        atomicAdd(&g_geo[s * 2 + 1], (double)oob);
    }
}

// ---------------- finalize: label correction + weighted combine ----------------
__global__ void k_final(const float* __restrict__ cls, const int* __restrict__ glab,
                        int N, float* __restrict__ out)
{
    if (threadIdx.x != 0 || blockIdx.x != 0) return;
    double corr = 0.0;
    int mr = g_pos_cnt[1];
    for (int q = 0; q < mr; q++) {
        int j   = g_pos_idx[1][q];
        int lab = glab[g_pos_gt[1][q]];
        corr += (double)cls[(size_t)j * 16 + 0] - (double)cls[(size_t)j * 16 + lab];
    }
    double cls_loss = (g_cls_sum + corr) / (double)N;
    double ni = (double)max(g_pos_cnt[0], 1);
    double nr = (double)max(g_pos_cnt[1], 1);
    double loss = cls_loss
                + 0.3  * (g_geo[0] / ni)
                + 1.0  * (g_geo[2] / nr)
                + 0.05 * (g_geo[1] / ni)
                + 0.1  * (g_geo[3] / nr);
    out[0] = (float)loss;
}

// ---------------- launch ----------------
extern "C" void kernel_launch(void* const* d_in, const int* in_sizes, int n_in,
                              void* d_out, int out_size)
{
    const float* rpi  = (const float*)d_in[0];
    const float* rpr  = (const float*)d_in[1];
    const float* cls  = (const float*)d_in[2];
    const float* pstr = (const float*)d_in[3];
    const float* gtb  = (const float*)d_in[4];
    const int*   glab = (const int*)d_in[5];
    float* out = (float*)d_out;

    int N = in_sizes[3];          // points_stride element count
    int K = in_sizes[5];          // gt_labels element count (=64)
    if (K > KMAX) K = KMAX;

    k_prep<<<1, 64>>>(gtb, K);
    k_assign<<<(N + 255) / 256, 256>>>(rpi, rpr, cls, pstr, N, K);
    k_scan<<<1, 32>>>(K);
    k_geom<<<2 * KMAX, 32>>>(rpi, rpr, gtb);
    k_final<<<1, 32>>>(cls, glab, N, out);
}

// round 4
// speedup vs baseline: 1.7183x; 1.0171x over previous
#include <cuda_runtime.h>
#include <math.h>
#include <stdint.h>

#define KMAX 64
#define BUF  16
#define NLVL 5          // levels 3..7

// ---------------- device-global scratch (no allocations allowed) ----------------
__device__ float g_gt_cx[KMAX], g_gt_cy[KMAX], g_gt_rw[KMAX], g_gt_rh[KMAX];
__device__ int   g_lvl_cnt[NLVL];
__device__ int   g_lvl_list[NLVL][KMAX];
__device__ unsigned long long g_best[2][KMAX];   // packed (dd2_bits<<32)|point_idx, min-reduced
__device__ int    g_pos_idx[2][KMAX];            // point index of positives
__device__ int    g_pos_gt[2][KMAX];             // assigned gt index
__device__ int    g_pos_cnt[2];
__device__ double g_cls_sum;                     // sum over n of (lse_n - cls[n,0])
__device__ double g_geo[4];                      // [loc_i, sc_i, loc_r, sc_r] raw sums

__device__ __forceinline__ float f_inf() { return __int_as_float(0x7f800000); }

// Non-FMA cross product: matches XLA's unfused mul/sub semantics exactly.
__device__ __forceinline__ float cross_nf(float ax, float ay, float bx, float by)
{
    return __fsub_rn(__fmul_rn(ax, by), __fmul_rn(ay, bx));
}

// ---------------- prep: per-gt center/recip-size/level buckets + reset ----------------
__global__ void k_prep(const float* __restrict__ gt, int K)
{
    __shared__ int s_lvl[KMAX];
    int k = threadIdx.x;
    if (k == 0) { g_cls_sum = 0.0; g_pos_cnt[0] = 0; g_pos_cnt[1] = 0; }
    if (k < 4) g_geo[k] = 0.0;
    if (k < KMAX) { g_best[0][k] = ~0ull; g_best[1][k] = ~0ull; }
    if (k < K) {
        const float* r = gt + 8 * k;
        float xmn = fminf(fminf(r[0], r[2]), fminf(r[4], r[6]));
        float xmx = fmaxf(fmaxf(r[0], r[2]), fmaxf(r[4], r[6]));
        float ymn = fminf(fminf(r[1], r[3]), fminf(r[5], r[7]));
        float ymx = fmaxf(fmaxf(r[1], r[3]), fmaxf(r[5], r[7]));
        float w = fmaxf(__fsub_rn(xmx, xmn), 1e-6f);
        float h = fmaxf(__fsub_rn(ymx, ymn), 1e-6f);
        g_gt_cx[k] = __fmul_rn(__fadd_rn(xmn, xmx), 0.5f);
        g_gt_cy[k] = __fmul_rn(__fadd_rn(ymn, ymx), 0.5f);
        g_gt_rw[k] = __fdiv_rn(1.0f, w);
        g_gt_rh[k] = __fdiv_rn(1.0f, h);
        float lv = __fmul_rn(__fadd_rn(log2f(__fdiv_rn(w, 4.0f)),
                                       log2f(__fdiv_rn(h, 4.0f))), 0.5f);
        int lvl = (int)lv;                           // trunc toward zero (positive here)
        lvl = max(3, min(7, lvl));
        s_lvl[k] = lvl;
    }
    __syncthreads();
    if (k == 0) {                                    // serial bucket build, ascending k
        int cnt[NLVL];
        #pragma unroll
        for (int l = 0; l < NLVL; l++) cnt[l] = 0;
        for (int q = 0; q < K; q++) {
            int li = s_lvl[q] - 3;
            g_lvl_list[li][cnt[li]++] = q;
        }
        #pragma unroll
        for (int l = 0; l < NLVL; l++) g_lvl_cnt[l] = cnt[l];
    }
}

// ---------------- assign (level-bucketed, squared-distance keys) + cls lse ----------------
__global__ void k_assign(const float* __restrict__ rpi, const float* __restrict__ rpr,
                         const float* __restrict__ cls, const float* __restrict__ pstr,
                         int N, int K)
{
    __shared__ unsigned long long sb[2][KMAX];
    __shared__ float scx[KMAX], scy[KMAX], srw[KMAX], srh[KMAX];
    __shared__ int   slist[NLVL][KMAX];
    __shared__ int   scnt[NLVL];
    __shared__ double swsum[8];

    int t = threadIdx.x;
    for (int k = t; k < KMAX; k += blockDim.x) { sb[0][k] = ~0ull; sb[1][k] = ~0ull; }
    for (int k = t; k < K; k += blockDim.x) {
        scx[k] = g_gt_cx[k]; scy[k] = g_gt_cy[k];
        srw[k] = g_gt_rw[k]; srh[k] = g_gt_rh[k];
    }
    if (t < NLVL) scnt[t] = g_lvl_cnt[t];
    for (int q = t; q < NLVL * KMAX; q += blockDim.x)
        slist[q / KMAX][q % KMAX] = g_lvl_list[q / KMAX][q % KMAX];
    __syncthreads();

    int n = blockIdx.x * blockDim.x + t;
    double lterm = 0.0;
    if (n < N) {
        int li = (31 - __clz((int)pstr[n])) - 3;      // stride is an exact power of two
        float2 pi = __ldg((const float2*)(rpi + (size_t)n * 18 + 8));
        float2 pr = __ldg((const float2*)(rpr + (size_t)n * 18 + 8));
        unsigned un = (unsigned)n;
        int cnt = scnt[li];
        // squared distance with reciprocal multiply: preserves the argmin ordering
        // (winner/runner-up gaps >> rounding except measure-zero near-ties)
        for (int m = 0; m < cnt; m++) {
            int k = slist[li][m];
            float dxi = __fmul_rn(__fsub_rn(pi.x, scx[k]), srw[k]);
            float dyi = __fmul_rn(__fsub_rn(pi.y, scy[k]), srh[k]);
            float ddi = __fadd_rn(__fmul_rn(dxi, dxi), __fmul_rn(dyi, dyi));
            unsigned long long ki = ((unsigned long long)__float_as_uint(ddi) << 32) | un;
            if (ki < sb[0][k]) atomicMin(&sb[0][k], ki);

            float dxr = __fmul_rn(__fsub_rn(pr.x, scx[k]), srw[k]);
            float dyr = __fmul_rn(__fsub_rn(pr.y, scy[k]), srh[k]);
            float ddr = __fadd_rn(__fmul_rn(dxr, dxr), __fmul_rn(dyr, dyr));
            unsigned long long kr = ((unsigned long long)__float_as_uint(ddr) << 32) | un;
            if (kr < sb[1][k]) atomicMin(&sb[1][k], kr);
        }
        // logsumexp over 16 classes (continuous path -> fast exp/log is fine)
        const float4* c4 = (const float4*)(cls + (size_t)n * 16);
        float v[16];
        #pragma unroll
        for (int j = 0; j < 4; j++) {
            float4 f = __ldg(c4 + j);
            v[4 * j] = f.x; v[4 * j + 1] = f.y; v[4 * j + 2] = f.z; v[4 * j + 3] = f.w;
        }
        float m = v[0];
        #pragma unroll
        for (int j = 1; j < 16; j++) m = fmaxf(m, v[j]);
        float s = 0.f;
        #pragma unroll
        for (int j = 0; j < 16; j++) s += __expf(v[j] - m);
        lterm = (double)((m + __logf(s)) - v[0]);
    }
    // warp-reduce, then block-reduce in shared, ONE global atomic per block
    for (int o = 16; o; o >>= 1) lterm += __shfl_down_sync(0xffffffffu, lterm, o);
    if ((t & 31) == 0) swsum[t >> 5] = lterm;
    __syncthreads();
    if (t == 0) {
        double bs = 0.0;
        int nw = (blockDim.x + 31) >> 5;
        for (int q = 0; q < nw; q++) bs += swsum[q];
        atomicAdd(&g_cls_sum, bs);
    }
    for (int k = t; k < K; k += blockDim.x) {
        if (sb[0][k] != ~0ull) atomicMin(&g_best[0][k], sb[0][k]);
        if (sb[1][k] != ~0ull) atomicMin(&g_best[1][k], sb[1][k]);
    }
}

// ---------------- sequential scan replay (order matters, 64 steps, trivial) ----------------
__global__ void k_scan(int K)
{
    if (threadIdx.x != 0 || blockIdx.x != 0) return;
    for (int s = 0; s < 2; s++) {
        int   jl[KMAX], gl[KMAX];
        float dl[KMAX];
        int m = 0;
        for (int k = 0; k < K; k++) {
            unsigned long long key = g_best[s][k];
            if (key == ~0ull) continue;               // no candidate: md=inf, never wins
            float md = __uint_as_float((unsigned)(key >> 32));
            int j = (int)(unsigned)(key & 0xffffffffu);
            int p = -1;
            for (int q = 0; q < m; q++) if (jl[q] == j) { p = q; break; }
            if (p < 0) { jl[m] = j; gl[m] = k; dl[m] = md; m++; }
            else if (md < dl[p]) { gl[p] = k; dl[p] = md; }
        }
        g_pos_cnt[s] = m;
        for (int q = 0; q < m; q++) { g_pos_idx[s][q] = jl[q]; g_pos_gt[s][q] = gl[q]; }
    }
}

// ---------------- geometry ----------------
__device__ float shoelace16(const float2* V, int c)
{
    float s = 0.f;
    #pragma unroll
    for (int i = 0; i < BUF; i++) {
        if (i >= c) continue;
        int nxt = (i + 1 < c) ? i + 1 : 0;
        s = __fadd_rn(s, cross_nf(V[i].x, V[i].y, V[nxt].x, V[nxt].y));
    }
    return 0.5f * fabsf(s);
}

// warp-parallel convex hull, reference semantics (bit-exact as before)
__device__ int hull_warp_sorted(const float2* sP, int n, float* skey, float2* sV, int lane)
{
    bool h = false;
    if (lane < n) {
        float pix = sP[lane].x, piy = sP[lane].y;
        for (int j = 0; j < n && !h; j++) {
            if (j == lane) continue;
            float dx = __fsub_rn(sP[j].x, pix), dy = __fsub_rn(sP[j].y, piy);
            float mn = f_inf();
            for (int k = 0; k < n; k++) {
                float cr = cross_nf(dx, dy, __fsub_rn(sP[k].x, pix), __fsub_rn(sP[k].y, piy));
                mn = fminf(mn, cr);            // min: order-independent
            }
            if (mn >= -1e-6f) h = true;
        }
    }
    unsigned mask = __ballot_sync(0xffffffffu, h);
    int cnt = __popc(mask);
    // centroid: serial ascending i on every lane (matches reference sum order)
    float sx = 0.f, sy = 0.f;
    for (int i = 0; i < n; i++)
        if ((mask >> i) & 1) { sx = __fadd_rn(sx, sP[i].x); sy = __fadd_rn(sy, sP[i].y); }
    float cd = (float)(cnt > 0 ? cnt : 1);
    float cenx = __fdiv_rn(sx, cd), ceny = __fdiv_rn(sy, cd);
    if (lane < n)
        skey[lane] = h ? atan2f(__fsub_rn(sP[lane].y, ceny), __fsub_rn(sP[lane].x, cenx))
                       : f_inf();
    __syncwarp();
    if (lane == 0) {
        int ord[13];
        for (int i = 0; i < n; i++) ord[i] = i;
        for (int i = 1; i < n; i++) {                 // stable insertion sort
            int oi = ord[i]; float ki = skey[oi]; int j = i - 1;
            while (j >= 0 && skey[ord[j]] > ki) { ord[j + 1] = ord[j]; j--; }
            ord[j + 1] = oi;
        }
        for (int i = 0; i < n; i++) sV[i] = sP[ord[i]];
        for (int i = n; i < BUF; i++) sV[i] = make_float2(0.f, 0.f);
    }
    __syncwarp();
    return cnt;
}

// warp-parallel Sutherland-Hodgman: per-element math identical to serial version
__device__ void clip_warp(float2* V, int& c, float2 a, float2 b, int lane, float2* scratch)
{
    float ex = __fsub_rn(b.x, a.x), ey = __fsub_rn(b.y, a.y);
    int cc = c;
    bool active = (lane < BUF) && (lane < cc);
    int nxt = (lane + 1 < cc) ? lane + 1 : 0;
    float2 cur = active ? V[lane] : make_float2(0.f, 0.f);
    float2 nx  = active ? V[nxt]  : make_float2(0.f, 0.f);
    float s_cur = cross_nf(ex, ey, __fsub_rn(cur.x, a.x), __fsub_rn(cur.y, a.y));
    float s_nxt = cross_nf(ex, ey, __fsub_rn(nx.x,  a.x), __fsub_rn(nx.y,  a.y));
    bool in_cur = s_cur >= 0.f, in_nxt = s_nxt >= 0.f;
    float den = __fsub_rn(s_cur, s_nxt);
    float t = (fabsf(den) > 1e-9f) ? __fdiv_rn(s_cur, den) : 0.f;
    float2 ipt = make_float2(__fadd_rn(cur.x, __fmul_rn(t, __fsub_rn(nx.x, cur.x))),
                             __fadd_rn(cur.y, __fmul_rn(t, __fsub_rn(nx.y, cur.y))));
    bool f_int = active && (in_cur != in_nxt);
    bool f_nxt = active && in_nxt;
    unsigned bi = __ballot_sync(0xffffffffu, f_int);
    unsigned bn = __ballot_sync(0xffffffffu, f_nxt);
    unsigned below = (1u << lane) - 1u;
    int pos_i = __popc(bi & below) + __popc(bn & below);  // slot order (2i, 2i+1) preserved
    int pos_n = pos_i + (f_int ? 1 : 0);
    int nc = __popc(bi) + __popc(bn);
    __syncwarp();
    if (f_int && pos_i < BUF) scratch[pos_i] = ipt;
    if (f_nxt && pos_n < BUF) scratch[pos_n] = nx;
    __syncwarp();
    if (lane < BUF) V[lane] = (lane < nc) ? scratch[lane] : make_float2(0.f, 0.f);
    __syncwarp();
    c = nc;
}

// one task per block, 2 warps: warp0 = order+predhull+clip+oob, warp1 = big hull
__global__ void k_geom(const float* __restrict__ rpi, const float* __restrict__ rpr,
                       const float* __restrict__ gtb)
{
    __shared__ float2 sP9[9];
    __shared__ float2 sGT[4];     // raw gt corners
    __shared__ float2 sG[4];      // CCW-ordered gt corners
    __shared__ float2 sVa[BUF];   // pred hull -> clip polygon (warp0)
    __shared__ float2 sScrA[BUF];
    __shared__ float  sKeyA[13];
    __shared__ float2 sPtsB[13];  // warp1: concat hull input
    __shared__ float2 sVb[BUF];
    __shared__ float  sKeyB[13];
    __shared__ float  s_apred, s_agt, s_aint, s_ahull;

    int tid  = threadIdx.x;
    int lane = tid & 31;
    int w    = tid >> 5;
    int b = blockIdx.x;
    int s = (b >= KMAX) ? 1 : 0;
    int m = b - s * KMAX;
    if (m >= g_pos_cnt[s]) return;
    const float* rp = s ? rpr : rpi;
    int j  = g_pos_idx[s][m];
    int gi = g_pos_gt[s][m];
    const float* g8  = gtb + 8 * gi;
    const float* p18 = rp + (size_t)j * 18;

    if (tid < 4) sGT[tid] = make_float2(g8[2 * tid], g8[2 * tid + 1]);
    if (tid >= 4 && tid < 13) sP9[tid - 4] = make_float2(p18[2 * (tid - 4)], p18[2 * (tid - 4) + 1]);
    __syncthreads();

    if (w == 1) {
        // big hull of concat(gt4_original, p9)
        if (lane < 4)  sPtsB[lane] = sGT[lane];
        if (lane >= 4 && lane < 13) sPtsB[lane] = sP9[lane - 4];
        __syncwarp();
        int ch = hull_warp_sorted(sPtsB, 13, sKeyB, sVb, lane);
        if (lane == 0) s_ahull = shoelace16(sVb, ch);
    } else {
        // order gt corners CCW by angle around mean (lane 0, stable sort)
        if (lane == 0) {
            float cmx = (sGT[0].x + sGT[1].x + sGT[2].x + sGT[3].x) * 0.25f;
            float cmy = (sGT[0].y + sGT[1].y + sGT[2].y + sGT[3].y) * 0.25f;
            float ang[4]; int o4[4] = {0, 1, 2, 3};
            #pragma unroll
            for (int i = 0; i < 4; i++)
                ang[i] = atan2f(__fsub_rn(sGT[i].y, cmy), __fsub_rn(sGT[i].x, cmx));
            for (int i = 1; i < 4; i++) {
                int oi = o4[i]; float ki = ang[oi]; int jj = i - 1;
                while (jj >= 0 && ang[o4[jj]] > ki) { o4[jj + 1] = o4[jj]; jj--; }
                o4[jj + 1] = oi;
            }
            #pragma unroll
            for (int i = 0; i < 4; i++) sG[i] = sGT[o4[i]];
        }
        __syncwarp();
        // prediction hull (9 points)
        int c = hull_warp_sorted(sP9, 9, sKeyA, sVa, lane);
        if (lane == 0) {
            s_apred = shoelace16(sVa, c);
            float sgt = 0.f;
            #pragma unroll
            for (int i = 0; i < 4; i++) {
                int nx = (i + 1 < 4) ? i + 1 : 0;
                sgt = __fadd_rn(sgt, cross_nf(sG[i].x, sG[i].y, sG[nx].x, sG[nx].y));
            }
            s_agt = 0.5f * fabsf(sgt);
        }
        // clip by the 4 gt edges (warp-parallel; needs sG -> after syncwarp; reads of
        // sVa by all lanes complete before writes, guarded by syncwarps inside)
        for (int e = 0; e < 4; e++) clip_warp(sVa, c, sG[e], sG[(e + 1) & 3], lane, sScrA);
        if (lane == 0) s_aint = shoelace16(sVa, c);
    }
    __syncthreads();

    if (tid == 0) {
        float a_pred = s_apred, a_gt = s_agt, a_int = s_aint, a_hull = s_ahull;
        float uni = __fsub_rn(__fadd_rn(a_pred, a_gt), a_int);
        float iou = __fdiv_rn(a_int, __fadd_rn(uni, 1e-16f));
        float giou = __fsub_rn(iou, __fdiv_rn(__fsub_rn(a_hull, uni),
                                              __fadd_rn(a_hull, 1e-16f)));
        float gl = __fsub_rn(1.0f, giou);

        // out-of-box penalty (serial: matches reference reduce order)
        float acc = 0.f;
        #pragma unroll
        for (int p = 0; p < 9; p++) {
            float mx = -f_inf();
            #pragma unroll
            for (int e = 0; e < 4; e++) {
                float ex = __fsub_rn(sG[(e + 1) & 3].x, sG[e].x);
                float ey = __fsub_rn(sG[(e + 1) & 3].y, sG[e].y);
                float num = cross_nf(ex, ey, __fsub_rn(sP9[p].x, sG[e].x),
                                             __fsub_rn(sP9[p].y, sG[e].y));
                float sv = __fdiv_rn(num,
                    __fadd_rn(__fsqrt_rn(__fadd_rn(__fmul_rn(ex, ex), __fmul_rn(ey, ey))),
                              1e-9f));
                mx = fmaxf(mx, -sv);
            }
            acc = __fadd_rn(acc, fmaxf(mx, 0.f));
        }
        float oob = __fdiv_rn(acc, 9.0f);

        atomicAdd(&g_geo[s * 2 + 0], (double)gl);
        atomicAdd(&g_geo[s * 2 + 1], (double)oob);
    }
}

// ---------------- finalize: label correction + weighted combine ----------------
__global__ void k_final(const float* __restrict__ cls, const int* __restrict__ glab,
                        int N, float* __restrict__ out)
{
    if (threadIdx.x != 0 || blockIdx.x != 0) return;
    double corr = 0.0;
    int mr = g_pos_cnt[1];
    for (int q = 0; q < mr; q++) {
        int j   = g_pos_idx[1][q];
        int lab = glab[g_pos_gt[1][q]];
        corr += (double)cls[(size_t)j * 16 + 0] - (double)cls[(size_t)j * 16 + lab];
    }
    double cls_loss = (g_cls_sum + corr) / (double)N;
    double ni = (double)max(g_pos_cnt[0], 1);
    double nr = (double)max(g_pos_cnt[1], 1);
    double loss = cls_loss
                + 0.3  * (g_geo[0] / ni)
                + 1.0  * (g_geo[2] / nr)
                + 0.05 * (g_geo[1] / ni)
                + 0.1  * (g_geo[3] / nr);
    out[0] = (float)loss;
}

// ---------------- launch ----------------
extern "C" void kernel_launch(void* const* d_in, const int* in_sizes, int n_in,
                              void* d_out, int out_size)
{
    const float* rpi  = (const float*)d_in[0];
    const float* rpr  = (const float*)d_in[1];
    const float* cls  = (const float*)d_in[2];
    const float* pstr = (const float*)d_in[3];
    const float* gtb  = (const float*)d_in[4];
    const int*   glab = (const int*)d_in[5];
    float* out = (float*)d_out;

    int N = in_sizes[3];          // points_stride element count
    int K = in_sizes[5];          // gt_labels element count (=64)
    if (K > KMAX) K = KMAX;

    k_prep<<<1, 64>>>(gtb, K);
    k_assign<<<(N + 255) / 256, 256>>>(rpi, rpr, cls, pstr, N, K);
    k_scan<<<1, 32>>>(K);
    k_geom<<<2 * KMAX, 64>>>(rpi, rpr, gtb);
    k_final<<<1, 32>>>(cls, glab, N, out);
}

// round 5
// speedup vs baseline: 1.9800x; 1.1523x over previous
#include <cuda_runtime.h>
#include <math.h>
#include <stdint.h>

#define KMAX 64
#define BUF  16
#define NLVL 5          // levels 3..7
#define NB   (NLVL * KMAX)

// ---------------- device-global scratch (no allocations allowed) ----------------
__device__ float4 g_bkt[NB];                     // bucketed gt: {cx, cy, 1/w, 1/h}
__device__ int    g_lvl_cnt[NLVL];
__device__ int    g_k2b[KMAX];                   // original k -> bucket slot
__device__ unsigned long long g_best[2][NB];     // packed (dd2_bits<<32)|point_idx
__device__ int    g_pos_idx[2][KMAX];            // point index of positives
__device__ int    g_pos_gt[2][KMAX];             // assigned gt index
__device__ int    g_pos_cnt[2];
__device__ double g_cls_sum;                     // sum over n of (lse_n - cls[n,0])
__device__ double g_corr;                        // cls label correction
__device__ double g_geo[4];                      // [loc_i, sc_i, loc_r, sc_r] raw sums

__device__ __forceinline__ float f_inf() { return __int_as_float(0x7f800000); }

// Non-FMA cross product: matches XLA's unfused mul/sub semantics exactly.
__device__ __forceinline__ float cross_nf(float ax, float ay, float bx, float by)
{
    return __fsub_rn(__fmul_rn(ax, by), __fmul_rn(ay, bx));
}

// ---------------- prep: per-gt center/recip-size/level buckets + reset ----------------
__global__ void k_prep(const float* __restrict__ gt, int K)
{
    __shared__ int    s_lvl[KMAX];
    __shared__ float4 s_b[KMAX];
    int k = threadIdx.x;
    if (k == 0) { g_cls_sum = 0.0; g_corr = 0.0; g_pos_cnt[0] = 0; g_pos_cnt[1] = 0; }
    if (k < 4) g_geo[k] = 0.0;
    for (int q = k; q < NB; q += blockDim.x) { g_best[0][q] = ~0ull; g_best[1][q] = ~0ull; }
    if (k < K) {
        const float* r = gt + 8 * k;
        float xmn = fminf(fminf(r[0], r[2]), fminf(r[4], r[6]));
        float xmx = fmaxf(fmaxf(r[0], r[2]), fmaxf(r[4], r[6]));
        float ymn = fminf(fminf(r[1], r[3]), fminf(r[5], r[7]));
        float ymx = fmaxf(fmaxf(r[1], r[3]), fmaxf(r[5], r[7]));
        float w = fmaxf(__fsub_rn(xmx, xmn), 1e-6f);
        float h = fmaxf(__fsub_rn(ymx, ymn), 1e-6f);
        float4 bq;
        bq.x = __fmul_rn(__fadd_rn(xmn, xmx), 0.5f);
        bq.y = __fmul_rn(__fadd_rn(ymn, ymx), 0.5f);
        bq.z = __fdiv_rn(1.0f, w);
        bq.w = __fdiv_rn(1.0f, h);
        s_b[k] = bq;
        float lv = __fmul_rn(__fadd_rn(log2f(__fdiv_rn(w, 4.0f)),
                                       log2f(__fdiv_rn(h, 4.0f))), 0.5f);
        int lvl = (int)lv;                           // trunc toward zero (positive here)
        lvl = max(3, min(7, lvl));
        s_lvl[k] = lvl;
    }
    __syncthreads();
    if (k == 0) {                                    // serial bucket build, ascending k
        int cnt[NLVL];
        #pragma unroll
        for (int l = 0; l < NLVL; l++) cnt[l] = 0;
        for (int q = 0; q < K; q++) {
            int li = s_lvl[q] - 3;
            int slot = li * KMAX + cnt[li];
            g_bkt[slot] = s_b[q];
            g_k2b[q] = slot;
            cnt[li]++;
        }
        #pragma unroll
        for (int l = 0; l < NLVL; l++) g_lvl_cnt[l] = cnt[l];
    }
}

// ---------------- assign (level-bucketed float4, squared-distance keys) + cls lse ----------------
__global__ void __launch_bounds__(512) k_assign(
    const float* __restrict__ rpi, const float* __restrict__ rpr,
    const float* __restrict__ cls, const float* __restrict__ pstr, int N)
{
    __shared__ unsigned long long sb0[NB], sb1[NB];
    __shared__ float4 sbkt[NB];
    __shared__ int    scnt[NLVL];
    __shared__ double swsum[16];

    int t = threadIdx.x;
    for (int q = t; q < NB; q += blockDim.x) {
        sb0[q] = ~0ull; sb1[q] = ~0ull;
        sbkt[q] = g_bkt[q];
    }
    if (t < NLVL) scnt[t] = g_lvl_cnt[t];
    __syncthreads();

    int n = blockIdx.x * blockDim.x + t;
    double lterm = 0.0;
    if (n < N) {
        int li = (31 - __clz((int)pstr[n])) - 3;      // stride is an exact power of two
        float2 pi = __ldg((const float2*)(rpi + (size_t)n * 18 + 8));
        float2 pr = __ldg((const float2*)(rpr + (size_t)n * 18 + 8));
        unsigned un = (unsigned)n;
        int cnt  = scnt[li];
        int base = li * KMAX;
        // squared distance with reciprocal multiply: preserves the argmin ordering
        for (int m = 0; m < cnt; m++) {
            int slot = base + m;
            float4 gq = sbkt[slot];
            float dxi = __fmul_rn(__fsub_rn(pi.x, gq.x), gq.z);
            float dyi = __fmul_rn(__fsub_rn(pi.y, gq.y), gq.w);
            float ddi = __fadd_rn(__fmul_rn(dxi, dxi), __fmul_rn(dyi, dyi));
            unsigned long long ki = ((unsigned long long)__float_as_uint(ddi) << 32) | un;
            if (ki < sb0[slot]) atomicMin(&sb0[slot], ki);

            float dxr = __fmul_rn(__fsub_rn(pr.x, gq.x), gq.z);
            float dyr = __fmul_rn(__fsub_rn(pr.y, gq.y), gq.w);
            float ddr = __fadd_rn(__fmul_rn(dxr, dxr), __fmul_rn(dyr, dyr));
            unsigned long long kr = ((unsigned long long)__float_as_uint(ddr) << 32) | un;
            if (kr < sb1[slot]) atomicMin(&sb1[slot], kr);
        }
        // logsumexp over 16 classes (continuous path -> fast exp/log is fine)
        const float4* c4 = (const float4*)(cls + (size_t)n * 16);
        float v[16];
        #pragma unroll
        for (int j = 0; j < 4; j++) {
            float4 f = __ldg(c4 + j);
            v[4 * j] = f.x; v[4 * j + 1] = f.y; v[4 * j + 2] = f.z; v[4 * j + 3] = f.w;
        }
        float m = v[0];
        #pragma unroll
        for (int j = 1; j < 16; j++) m = fmaxf(m, v[j]);
        float s = 0.f;
        #pragma unroll
        for (int j = 0; j < 16; j++) s += __expf(v[j] - m);
        lterm = (double)((m + __logf(s)) - v[0]);
    }
    // warp-reduce, then block-reduce in shared, ONE global atomic per block
    for (int o = 16; o; o >>= 1) lterm += __shfl_down_sync(0xffffffffu, lterm, o);
    if ((t & 31) == 0) swsum[t >> 5] = lterm;
    __syncthreads();
    if (t == 0) {
        double bs = 0.0;
        int nw = (blockDim.x + 31) >> 5;
        for (int q = 0; q < nw; q++) bs += swsum[q];
        atomicAdd(&g_cls_sum, bs);
    }
    for (int q = t; q < NB; q += blockDim.x) {
        if (sb0[q] != ~0ull) atomicMin(&g_best[0][q], sb0[q]);
        if (sb1[q] != ~0ull) atomicMin(&g_best[1][q], sb1[q]);
    }
}

// ---------------- scan replay (prefetched to shared) + parallel cls correction ----------------
__global__ void k_scan(const float* __restrict__ cls, const int* __restrict__ glab, int K)
{
    __shared__ unsigned long long skey[2][KMAX];
    __shared__ int s_jl[KMAX], s_gl[KMAX];
    __shared__ int s_m;
    int t = threadIdx.x;

    // parallel prefetch: one latency hit instead of 128 serialized ones
    for (int q = t; q < 2 * KMAX; q += blockDim.x) {
        int s = q >> 6, k = q & 63;
        skey[s][k] = (k < K) ? g_best[s][g_k2b[k]] : ~0ull;
    }
    __syncthreads();

    for (int s = 0; s < 2; s++) {
        if (t == 0) {
            int   jl[KMAX], gl[KMAX];
            float dl[KMAX];
            int m = 0;
            for (int k = 0; k < K; k++) {
                unsigned long long key = skey[s][k];
                if (key == ~0ull) continue;           // no candidate: md=inf, never wins
                float md = __uint_as_float((unsigned)(key >> 32));
                int j = (int)(unsigned)(key & 0xffffffffu);
                int p = -1;
                for (int q = 0; q < m; q++) if (jl[q] == j) { p = q; break; }
                if (p < 0) { jl[m] = j; gl[m] = k; dl[m] = md; m++; }
                else if (md < dl[p]) { gl[p] = k; dl[p] = md; }
            }
            s_m = m;
            g_pos_cnt[s] = m;
            for (int q = 0; q < m; q++) { s_jl[q] = jl[q]; s_gl[q] = gl[q]; }
        }
        __syncthreads();
        // parallel writeback of positives
        if (t < s_m) { g_pos_idx[s][t] = s_jl[t]; g_pos_gt[s][t] = s_gl[t]; }
        // stage 1 (refine): cls label correction, gathered in parallel
        if (s == 1) {
            double part = 0.0;
            if (t < s_m) {
                int j   = s_jl[t];
                int lab = glab[s_gl[t]];
                part = (double)cls[(size_t)j * 16 + 0] - (double)cls[(size_t)j * 16 + lab];
            }
            for (int o = 16; o; o >>= 1) part += __shfl_down_sync(0xffffffffu, part, o);
            if ((t & 31) == 0) atomicAdd(&g_corr, part);
        }
        __syncthreads();
    }
}

// ---------------- geometry ----------------
__device__ float shoelace16(const float2* V, int c)
{
    float s = 0.f;
    #pragma unroll
    for (int i = 0; i < BUF; i++) {
        if (i >= c) continue;
        int nxt = (i + 1 < c) ? i + 1 : 0;
        s = __fadd_rn(s, cross_nf(V[i].x, V[i].y, V[nxt].x, V[nxt].y));
    }
    return 0.5f * fabsf(s);
}

// warp-parallel convex hull, reference semantics (bit-exact)
__device__ int hull_warp_sorted(const float2* sP, int n, float* skey, float2* sV, int lane)
{
    bool h = false;
    if (lane < n) {
        float pix = sP[lane].x, piy = sP[lane].y;
        for (int j = 0; j < n && !h; j++) {
            if (j == lane) continue;
            float dx = __fsub_rn(sP[j].x, pix), dy = __fsub_rn(sP[j].y, piy);
            float mn = f_inf();
            for (int k = 0; k < n; k++) {
                float cr = cross_nf(dx, dy, __fsub_rn(sP[k].x, pix), __fsub_rn(sP[k].y, piy));
                mn = fminf(mn, cr);            // min: order-independent
            }
            if (mn >= -1e-6f) h = true;
        }
    }
    unsigned mask = __ballot_sync(0xffffffffu, h);
    int cnt = __popc(mask);
    float sx = 0.f, sy = 0.f;
    for (int i = 0; i < n; i++)
        if ((mask >> i) & 1) { sx = __fadd_rn(sx, sP[i].x); sy = __fadd_rn(sy, sP[i].y); }
    float cd = (float)(cnt > 0 ? cnt : 1);
    float cenx = __fdiv_rn(sx, cd), ceny = __fdiv_rn(sy, cd);
    if (lane < n)
        skey[lane] = h ? atan2f(__fsub_rn(sP[lane].y, ceny), __fsub_rn(sP[lane].x, cenx))
                       : f_inf();
    __syncwarp();
    if (lane == 0) {
        int ord[13];
        for (int i = 0; i < n; i++) ord[i] = i;
        for (int i = 1; i < n; i++) {                 // stable insertion sort
            int oi = ord[i]; float ki = skey[oi]; int j = i - 1;
            while (j >= 0 && skey[ord[j]] > ki) { ord[j + 1] = ord[j]; j--; }
            ord[j + 1] = oi;
        }
        for (int i = 0; i < n; i++) sV[i] = sP[ord[i]];
        for (int i = n; i < BUF; i++) sV[i] = make_float2(0.f, 0.f);
    }
    __syncwarp();
    return cnt;
}

// warp-parallel Sutherland-Hodgman: per-element math identical to serial version
__device__ void clip_warp(float2* V, int& c, float2 a, float2 b, int lane, float2* scratch)
{
    float ex = __fsub_rn(b.x, a.x), ey = __fsub_rn(b.y, a.y);
    int cc = c;
    bool active = (lane < BUF) && (lane < cc);
    int nxt = (lane + 1 < cc) ? lane + 1 : 0;
    float2 cur = active ? V[lane] : make_float2(0.f, 0.f);
    float2 nx  = active ? V[nxt]  : make_float2(0.f, 0.f);
    float s_cur = cross_nf(ex, ey, __fsub_rn(cur.x, a.x), __fsub_rn(cur.y, a.y));
    float s_nxt = cross_nf(ex, ey, __fsub_rn(nx.x,  a.x), __fsub_rn(nx.y,  a.y));
    bool in_cur = s_cur >= 0.f, in_nxt = s_nxt >= 0.f;
    float den = __fsub_rn(s_cur, s_nxt);
    float t = (fabsf(den) > 1e-9f) ? __fdiv_rn(s_cur, den) : 0.f;
    float2 ipt = make_float2(__fadd_rn(cur.x, __fmul_rn(t, __fsub_rn(nx.x, cur.x))),
                             __fadd_rn(cur.y, __fmul_rn(t, __fsub_rn(nx.y, cur.y))));
    bool f_int = active && (in_cur != in_nxt);
    bool f_nxt = active && in_nxt;
    unsigned bi = __ballot_sync(0xffffffffu, f_int);
    unsigned bn = __ballot_sync(0xffffffffu, f_nxt);
    unsigned below = (1u << lane) - 1u;
    int pos_i = __popc(bi & below) + __popc(bn & below);  // slot order (2i, 2i+1) preserved
    int pos_n = pos_i + (f_int ? 1 : 0);
    int nc = __popc(bi) + __popc(bn);
    __syncwarp();
    if (f_int && pos_i < BUF) scratch[pos_i] = ipt;
    if (f_nxt && pos_n < BUF) scratch[pos_n] = nx;
    __syncwarp();
    if (lane < BUF) V[lane] = (lane < nc) ? scratch[lane] : make_float2(0.f, 0.f);
    __syncwarp();
    c = nc;
}

// one task per block, 2 warps: warp0 = order+predhull+clip+oob, warp1 = big hull
__global__ void k_geom(const float* __restrict__ rpi, const float* __restrict__ rpr,
                       const float* __restrict__ gtb)
{
    __shared__ float2 sP9[9];
    __shared__ float2 sGT[4];     // raw gt corners
    __shared__ float2 sG[4];      // CCW-ordered gt corners
    __shared__ float2 sVa[BUF];   // pred hull -> clip polygon (warp0)
    __shared__ float2 sScrA[BUF];
    __shared__ float  sKeyA[13];
    __shared__ float2 sPtsB[13];  // warp1: concat hull input
    __shared__ float2 sVb[BUF];
    __shared__ float  sKeyB[13];
    __shared__ float  s_apred, s_agt, s_aint, s_ahull;

    int tid  = threadIdx.x;
    int lane = tid & 31;
    int w    = tid >> 5;
    int b = blockIdx.x;
    int s = (b >= KMAX) ? 1 : 0;
    int m = b - s * KMAX;
    if (m >= g_pos_cnt[s]) return;
    const float* rp = s ? rpr : rpi;
    int j  = g_pos_idx[s][m];
    int gi = g_pos_gt[s][m];
    const float* g8  = gtb + 8 * gi;
    const float* p18 = rp + (size_t)j * 18;

    if (tid < 4) sGT[tid] = make_float2(g8[2 * tid], g8[2 * tid + 1]);
    if (tid >= 4 && tid < 13) sP9[tid - 4] = make_float2(p18[2 * (tid - 4)], p18[2 * (tid - 4) + 1]);
    __syncthreads();

    if (w == 1) {
        if (lane < 4)  sPtsB[lane] = sGT[lane];
        if (lane >= 4 && lane < 13) sPtsB[lane] = sP9[lane - 4];
        __syncwarp();
        int ch = hull_warp_sorted(sPtsB, 13, sKeyB, sVb, lane);
        if (lane == 0) s_ahull = shoelace16(sVb, ch);
    } else {
        if (lane == 0) {
            float cmx = (sGT[0].x + sGT[1].x + sGT[2].x + sGT[3].x) * 0.25f;
            float cmy = (sGT[0].y + sGT[1].y + sGT[2].y + sGT[3].y) * 0.25f;
            float ang[4]; int o4[4] = {0, 1, 2, 3};
            #pragma unroll
            for (int i = 0; i < 4; i++)
                ang[i] = atan2f(__fsub_rn(sGT[i].y, cmy), __fsub_rn(sGT[i].x, cmx));
            for (int i = 1; i < 4; i++) {
                int oi = o4[i]; float ki = ang[oi]; int jj = i - 1;
                while (jj >= 0 && ang[o4[jj]] > ki) { o4[jj + 1] = o4[jj]; jj--; }
                o4[jj + 1] = oi;
            }
            #pragma unroll
            for (int i = 0; i < 4; i++) sG[i] = sGT[o4[i]];
        }
        __syncwarp();
        int c = hull_warp_sorted(sP9, 9, sKeyA, sVa, lane);
        if (lane == 0) {
            s_apred = shoelace16(sVa, c);
            float sgt = 0.f;
            #pragma unroll
            for (int i = 0; i < 4; i++) {
                int nx = (i + 1 < 4) ? i + 1 : 0;
                sgt = __fadd_rn(sgt, cross_nf(sG[i].x, sG[i].y, sG[nx].x, sG[nx].y));
            }
            s_agt = 0.5f * fabsf(sgt);
        }
        for (int e = 0; e < 4; e++) clip_warp(sVa, c, sG[e], sG[(e + 1) & 3], lane, sScrA);
        if (lane == 0) s_aint = shoelace16(sVa, c);
    }
    __syncthreads();

    if (tid == 0) {
        float a_pred = s_apred, a_gt = s_agt, a_int = s_aint, a_hull = s_ahull;
        float uni = __fsub_rn(__fadd_rn(a_pred, a_gt), a_int);
        float iou = __fdiv_rn(a_int, __fadd_rn(uni, 1e-16f));
        float giou = __fsub_rn(iou, __fdiv_rn(__fsub_rn(a_hull, uni),
                                              __fadd_rn(a_hull, 1e-16f)));
        float gl = __fsub_rn(1.0f, giou);

        float acc = 0.f;
        #pragma unroll
        for (int p = 0; p < 9; p++) {
            float mx = -f_inf();
            #pragma unroll
            for (int e = 0; e < 4; e++) {
                float ex = __fsub_rn(sG[(e + 1) & 3].x, sG[e].x);
                float ey = __fsub_rn(sG[(e + 1) & 3].y, sG[e].y);
                float num = cross_nf(ex, ey, __fsub_rn(sP9[p].x, sG[e].x),
                                             __fsub_rn(sP9[p].y, sG[e].y));
                float sv = __fdiv_rn(num,
                    __fadd_rn(__fsqrt_rn(__fadd_rn(__fmul_rn(ex, ex), __fmul_rn(ey, ey))),
                              1e-9f));
                mx = fmaxf(mx, -sv);
            }
            acc = __fadd_rn(acc, fmaxf(mx, 0.f));
        }
        float oob = __fdiv_rn(acc, 9.0f);

        atomicAdd(&g_geo[s * 2 + 0], (double)gl);
        atomicAdd(&g_geo[s * 2 + 1], (double)oob);
    }
}

// ---------------- finalize: trivial weighted combine (no loops, no chains) ----------------
__global__ void k_final(int N, float* __restrict__ out)
{
    if (threadIdx.x != 0 || blockIdx.x != 0) return;
    double cls_loss = (g_cls_sum + g_corr) / (double)N;
    double ni = (double)max(g_pos_cnt[0], 1);
    double nr = (double)max(g_pos_cnt[1], 1);
    double loss = cls_loss
                + 0.3  * (g_geo[0] / ni)
                + 1.0  * (g_geo[2] / nr)
                + 0.05 * (g_geo[1] / ni)
                + 0.1  * (g_geo[3] / nr);
    out[0] = (float)loss;
}

// ---------------- launch ----------------
extern "C" void kernel_launch(void* const* d_in, const int* in_sizes, int n_in,
                              void* d_out, int out_size)
{
    const float* rpi  = (const float*)d_in[0];
    const float* rpr  = (const float*)d_in[1];
    const float* cls  = (const float*)d_in[2];
    const float* pstr = (const float*)d_in[3];
    const float* gtb  = (const float*)d_in[4];
    const int*   glab = (const int*)d_in[5];
    float* out = (float*)d_out;

    int N = in_sizes[3];          // points_stride element count
    int K = in_sizes[5];          // gt_labels element count (=64)
    if (K > KMAX) K = KMAX;

    k_prep<<<1, 128>>>(gtb, K);
    k_assign<<<(N + 511) / 512, 512>>>(rpi, rpr, cls, pstr, N);
    k_scan<<<1, 64>>>(cls, glab, K);
    k_geom<<<2 * KMAX, 64>>>(rpi, rpr, gtb);
    k_final<<<1, 32>>>(N, out);
}

// round 6
// speedup vs baseline: 5.1287x; 2.5903x over previous
#include <cuda_runtime.h>
#include <math.h>
#include <stdint.h>

#define KMAX 64
#define BUF  16
#define NLVL 5          // levels 3..7
#define NB   (NLVL * KMAX)
#define NSM  148        // <= SM count on GB300 (152): all blocks co-resident
#define NTHR 512

// ---------------- device-global state (all zero-init; restored each launch) ----------------
__device__ unsigned g_bar_cnt;                   // barrier arrive counter
__device__ unsigned g_bar_gen;                   // barrier generation (monotonic across launches)
__device__ unsigned long long g_best[2][NB];     // INVERTED packed keys; 0 = empty (max-reduced)
__device__ int    g_pos_idx[2][KMAX];
__device__ int    g_pos_gt[2][KMAX];
__device__ int    g_pos_cnt[2];
__device__ double g_blk_lse[NSM];
__device__ double g_corr_val;
__device__ double g_task_gl[2][KMAX];
__device__ double g_task_oob[2][KMAX];

__device__ __forceinline__ float f_inf() { return __int_as_float(0x7f800000); }

// Non-FMA cross product: matches XLA's unfused mul/sub semantics exactly.
__device__ __forceinline__ float cross_nf(float ax, float ay, float bx, float by)
{
    return __fsub_rn(__fmul_rn(ax, by), __fmul_rn(ay, bx));
}

// Device-wide barrier: all NSM blocks co-resident (grid == NSM, launch_bounds caps regs).
__device__ __forceinline__ void grid_barrier()
{
    __syncthreads();
    if (threadIdx.x == 0) {
        volatile unsigned* vgen = &g_bar_gen;
        unsigned gen = *vgen;
        __threadfence();
        unsigned prev = atomicAdd(&g_bar_cnt, 1u);
        if (prev == NSM - 1) {
            g_bar_cnt = 0;
            __threadfence();
            atomicAdd(&g_bar_gen, 1u);
        } else {
            while (*vgen == gen) __nanosleep(64);
        }
    }
    __syncthreads();
}

// ---------------- geometry helpers (bit-identical to prior passing rounds) ----------------
__device__ float shoelace16(const float2* V, int c)
{
    float s = 0.f;
    #pragma unroll
    for (int i = 0; i < BUF; i++) {
        if (i >= c) continue;
        int nxt = (i + 1 < c) ? i + 1 : 0;
        s = __fadd_rn(s, cross_nf(V[i].x, V[i].y, V[nxt].x, V[nxt].y));
    }
    return 0.5f * fabsf(s);
}

__device__ int hull_warp_sorted(const float2* sP, int n, float* skey, float2* sV, int lane)
{
    bool h = false;
    if (lane < n) {
        float pix = sP[lane].x, piy = sP[lane].y;
        for (int j = 0; j < n && !h; j++) {
            if (j == lane) continue;
            float dx = __fsub_rn(sP[j].x, pix), dy = __fsub_rn(sP[j].y, piy);
            float mn = f_inf();
            for (int k = 0; k < n; k++) {
                float cr = cross_nf(dx, dy, __fsub_rn(sP[k].x, pix), __fsub_rn(sP[k].y, piy));
                mn = fminf(mn, cr);            // min: order-independent
            }
            if (mn >= -1e-6f) h = true;
        }
    }
    unsigned mask = __ballot_sync(0xffffffffu, h);
    int cnt = __popc(mask);
    float sx = 0.f, sy = 0.f;
    for (int i = 0; i < n; i++)
        if ((mask >> i) & 1) { sx = __fadd_rn(sx, sP[i].x); sy = __fadd_rn(sy, sP[i].y); }
    float cd = (float)(cnt > 0 ? cnt : 1);
    float cenx = __fdiv_rn(sx, cd), ceny = __fdiv_rn(sy, cd);
    if (lane < n)
        skey[lane] = h ? atan2f(__fsub_rn(sP[lane].y, ceny), __fsub_rn(sP[lane].x, cenx))
                       : f_inf();
    __syncwarp();
    if (lane == 0) {
        int ord[13];
        for (int i = 0; i < n; i++) ord[i] = i;
        for (int i = 1; i < n; i++) {                 // stable insertion sort
            int oi = ord[i]; float ki = skey[oi]; int j = i - 1;
            while (j >= 0 && skey[ord[j]] > ki) { ord[j + 1] = ord[j]; j--; }
            ord[j + 1] = oi;
        }
        for (int i = 0; i < n; i++) sV[i] = sP[ord[i]];
        for (int i = n; i < BUF; i++) sV[i] = make_float2(0.f, 0.f);
    }
    __syncwarp();
    return cnt;
}

__device__ void clip_warp(float2* V, int& c, float2 a, float2 b, int lane, float2* scratch)
{
    float ex = __fsub_rn(b.x, a.x), ey = __fsub_rn(b.y, a.y);
    int cc = c;
    bool active = (lane < BUF) && (lane < cc);
    int nxt = (lane + 1 < cc) ? lane + 1 : 0;
    float2 cur = active ? V[lane] : make_float2(0.f, 0.f);
    float2 nx  = active ? V[nxt]  : make_float2(0.f, 0.f);
    float s_cur = cross_nf(ex, ey, __fsub_rn(cur.x, a.x), __fsub_rn(cur.y, a.y));
    float s_nxt = cross_nf(ex, ey, __fsub_rn(nx.x,  a.x), __fsub_rn(nx.y,  a.y));
    bool in_cur = s_cur >= 0.f, in_nxt = s_nxt >= 0.f;
    float den = __fsub_rn(s_cur, s_nxt);
    float t = (fabsf(den) > 1e-9f) ? __fdiv_rn(s_cur, den) : 0.f;
    float2 ipt = make_float2(__fadd_rn(cur.x, __fmul_rn(t, __fsub_rn(nx.x, cur.x))),
                             __fadd_rn(cur.y, __fmul_rn(t, __fsub_rn(nx.y, cur.y))));
    bool f_int = active && (in_cur != in_nxt);
    bool f_nxt = active && in_nxt;
    unsigned bi = __ballot_sync(0xffffffffu, f_int);
    unsigned bn = __ballot_sync(0xffffffffu, f_nxt);
    unsigned below = (1u << lane) - 1u;
    int pos_i = __popc(bi & below) + __popc(bn & below);
    int pos_n = pos_i + (f_int ? 1 : 0);
    int nc = __popc(bi) + __popc(bn);
    __syncwarp();
    if (f_int && pos_i < BUF) scratch[pos_i] = ipt;
    if (f_nxt && pos_n < BUF) scratch[pos_n] = nx;
    __syncwarp();
    if (lane < BUF) V[lane] = (lane < nc) ? scratch[lane] : make_float2(0.f, 0.f);
    __syncwarp();
    c = nc;
}

// ---------------- the one fused kernel ----------------
__global__ void __launch_bounds__(NTHR) k_fused(
    const float* __restrict__ rpi, const float* __restrict__ rpr,
    const float* __restrict__ cls, const float* __restrict__ pstr,
    const float* __restrict__ gtb, const int* __restrict__ glab,
    int N, int K, float* __restrict__ out)
{
    // prep / assign
    __shared__ float  s_cx[KMAX], s_cy[KMAX], s_rw[KMAX], s_rh[KMAX];
    __shared__ int    s_lvl[KMAX];
    __shared__ float4 s_bkt[NB];
    __shared__ int    s_k2b[KMAX];
    __shared__ int    s_cnt[NLVL];
    __shared__ unsigned long long sb0[NB], sb1[NB];
    __shared__ double s_red[16];
    // scan
    __shared__ unsigned long long s_cmp[KMAX];
    __shared__ int s_j[KMAX];
    __shared__ int s_lead[KMAX];
    __shared__ int s_mcnt[2];
    // geom
    __shared__ float2 sP9[9];
    __shared__ float2 sGT[4];
    __shared__ float2 sG[4];
    __shared__ float2 sVa[BUF];
    __shared__ float2 sScrA[BUF];
    __shared__ float  sKeyA[13];
    __shared__ float2 sPtsB[13];
    __shared__ float2 sVb[BUF];
    __shared__ float  sKeyB[13];
    __shared__ float  s_apred, s_agt, s_aint, s_ahull;
    // final
    __shared__ double s_tgl[2 * KMAX], s_tob[2 * KMAX];

    const int tid = threadIdx.x;
    const int bid = blockIdx.x;

    // ---------------- Phase A: prep (redundant per block) + assign + lse ----------------
    for (int q = tid; q < NB; q += NTHR) { sb0[q] = 0ull; sb1[q] = 0ull; }
    if (tid < K) {
        const float* r = gtb + 8 * tid;
        float xmn = fminf(fminf(r[0], r[2]), fminf(r[4], r[6]));
        float xmx = fmaxf(fmaxf(r[0], r[2]), fmaxf(r[4], r[6]));
        float ymn = fminf(fminf(r[1], r[3]), fminf(r[5], r[7]));
        float ymx = fmaxf(fmaxf(r[1], r[3]), fmaxf(r[5], r[7]));
        float w = fmaxf(__fsub_rn(xmx, xmn), 1e-6f);
        float h = fmaxf(__fsub_rn(ymx, ymn), 1e-6f);
        s_cx[tid] = __fmul_rn(__fadd_rn(xmn, xmx), 0.5f);
        s_cy[tid] = __fmul_rn(__fadd_rn(ymn, ymx), 0.5f);
        s_rw[tid] = __fdiv_rn(1.0f, w);
        s_rh[tid] = __fdiv_rn(1.0f, h);
        float lv = __fmul_rn(__fadd_rn(log2f(__fdiv_rn(w, 4.0f)),
                                       log2f(__fdiv_rn(h, 4.0f))), 0.5f);
        int lvl = (int)lv;
        s_lvl[tid] = max(3, min(7, lvl));
    }
    __syncthreads();
    if (tid == 0) {                                  // serial bucket build, ascending k
        int cnt[NLVL];
        #pragma unroll
        for (int l = 0; l < NLVL; l++) cnt[l] = 0;
        for (int q = 0; q < K; q++) {
            int li = s_lvl[q] - 3;
            int slot = li * KMAX + cnt[li];
            s_bkt[slot] = make_float4(s_cx[q], s_cy[q], s_rw[q], s_rh[q]);
            s_k2b[q] = slot;
            cnt[li]++;
        }
        #pragma unroll
        for (int l = 0; l < NLVL; l++) s_cnt[l] = cnt[l];
    }
    __syncthreads();

    double lterm = 0.0;
    for (int n = bid * NTHR + tid; n < N; n += NSM * NTHR) {
        int li = (31 - __clz((int)pstr[n])) - 3;     // stride is an exact power of two
        float2 pi = __ldg((const float2*)(rpi + (size_t)n * 18 + 8));
        float2 pr = __ldg((const float2*)(rpr + (size_t)n * 18 + 8));
        unsigned un = (unsigned)n;
        int cnt  = s_cnt[li];
        int base = li * KMAX;
        for (int m = 0; m < cnt; m++) {
            int slot = base + m;
            float4 gq = s_bkt[slot];
            float dxi = __fmul_rn(__fsub_rn(pi.x, gq.x), gq.z);
            float dyi = __fmul_rn(__fsub_rn(pi.y, gq.y), gq.w);
            float ddi = __fadd_rn(__fmul_rn(dxi, dxi), __fmul_rn(dyi, dyi));
            unsigned long long ki = ~(((unsigned long long)__float_as_uint(ddi) << 32) | un);
            if (ki > sb0[slot]) atomicMax(&sb0[slot], ki);

            float dxr = __fmul_rn(__fsub_rn(pr.x, gq.x), gq.z);
            float dyr = __fmul_rn(__fsub_rn(pr.y, gq.y), gq.w);
            float ddr = __fadd_rn(__fmul_rn(dxr, dxr), __fmul_rn(dyr, dyr));
            unsigned long long kr = ~(((unsigned long long)__float_as_uint(ddr) << 32) | un);
            if (kr > sb1[slot]) atomicMax(&sb1[slot], kr);
        }
        const float4* c4 = (const float4*)(cls + (size_t)n * 16);
        float v[16];
        #pragma unroll
        for (int j = 0; j < 4; j++) {
            float4 f = __ldg(c4 + j);
            v[4 * j] = f.x; v[4 * j + 1] = f.y; v[4 * j + 2] = f.z; v[4 * j + 3] = f.w;
        }
        float mm = v[0];
        #pragma unroll
        for (int j = 1; j < 16; j++) mm = fmaxf(mm, v[j]);
        float ss = 0.f;
        #pragma unroll
        for (int j = 0; j < 16; j++) ss += __expf(v[j] - mm);
        lterm += (double)((mm + __logf(ss)) - v[0]);
    }
    for (int o = 16; o; o >>= 1) lterm += __shfl_down_sync(0xffffffffu, lterm, o);
    if ((tid & 31) == 0) s_red[tid >> 5] = lterm;
    __syncthreads();
    if (tid == 0) {
        double bs = 0.0;
        for (int q = 0; q < NTHR / 32; q++) bs += s_red[q];
        g_blk_lse[bid] = bs;
    }
    for (int q = tid; q < NB; q += NTHR) {
        if (sb0[q]) atomicMax(&g_best[0][q], sb0[q]);
        if (sb1[q]) atomicMax(&g_best[1][q], sb1[q]);
    }

    grid_barrier();   // --- barrier 1: assign complete ---

    // ---------------- Phase B (block 0): scan replay + cls correction ----------------
    if (bid == 0) {
        for (int s = 0; s < 2; s++) {
            if (tid < KMAX) {
                unsigned long long v = (tid < K) ? g_best[s][s_k2b[tid]] : 0ull;
                bool valid = (v != 0ull);
                unsigned long long pk = ~v;          // (md_bits<<32)|point_idx
                s_j[tid]   = valid ? (int)(unsigned)(pk & 0xffffffffu) : (-1 - tid);
                s_cmp[tid] = valid ? (((pk >> 32) << 32) | (unsigned)tid) : ~0ull; // (md,k)
            }
            __syncthreads();
            if (tid < KMAX) {
                int j = s_j[tid];
                bool lead = (j >= 0);
                if (lead)
                    for (int e = 0; e < tid; e++)
                        if (s_j[e] == j) { lead = false; break; }
                s_lead[tid] = lead ? 1 : 0;
            }
            __syncthreads();
            if (tid < K && s_lead[tid]) {
                int j = s_j[tid];
                unsigned long long best = s_cmp[tid];
                for (int e = 0; e < K; e++)
                    if (s_j[e] == j && s_cmp[e] < best) best = s_cmp[e];
                int pos = 0;
                for (int e = 0; e < tid; e++) pos += s_lead[e];
                g_pos_idx[s][pos] = j;
                g_pos_gt[s][pos]  = (int)(unsigned)(best & 0xffffffffu);
            }
            __syncthreads();
            if (tid == 0) {
                int m = 0;
                for (int e = 0; e < K; e++) m += s_lead[e];
                g_pos_cnt[s] = m;
                s_mcnt[s] = m;
            }
            __syncthreads();
        }
        // cls label correction over refine positives (parallel gather)
        double part = 0.0;
        if (tid < s_mcnt[1]) {
            int j   = g_pos_idx[1][tid];
            int lab = glab[g_pos_gt[1][tid]];
            part = (double)cls[(size_t)j * 16 + 0] - (double)cls[(size_t)j * 16 + lab];
        }
        for (int o = 16; o; o >>= 1) part += __shfl_down_sync(0xffffffffu, part, o);
        if ((tid & 31) == 0) s_red[tid >> 5] = part;
        __syncthreads();
        if (tid == 0) {
            double cs = 0.0;
            for (int q = 0; q < NTHR / 32; q++) cs += s_red[q];
            g_corr_val = cs;
        }
    }

    grid_barrier();   // --- barrier 2: positives ready ---

    // ---------------- Phase C (blocks 0..127): geometry, one task per block ----------------
    {
        int s = (bid >= KMAX) ? 1 : 0;
        int m = bid - s * KMAX;
        bool task = (bid < 2 * KMAX) && (m < g_pos_cnt[s]);
        int lane = tid & 31;
        int w    = tid >> 5;

        if (task) {
            const float* rp  = s ? rpr : rpi;
            int j  = g_pos_idx[s][m];
            int gi = g_pos_gt[s][m];
            const float* g8  = gtb + 8 * gi;
            const float* p18 = rp + (size_t)j * 18;
            if (tid < 4)  sGT[tid] = make_float2(g8[2 * tid], g8[2 * tid + 1]);
            if (tid >= 4 && tid < 13)
                sP9[tid - 4] = make_float2(p18[2 * (tid - 4)], p18[2 * (tid - 4) + 1]);
        }
        __syncthreads();

        if (task && w == 1) {
            if (lane < 4)  sPtsB[lane] = sGT[lane];
            if (lane >= 4 && lane < 13) sPtsB[lane] = sP9[lane - 4];
            __syncwarp();
            int ch = hull_warp_sorted(sPtsB, 13, sKeyB, sVb, lane);
            if (lane == 0) s_ahull = shoelace16(sVb, ch);
        } else if (task && w == 0) {
            if (lane == 0) {
                float cmx = (sGT[0].x + sGT[1].x + sGT[2].x + sGT[3].x) * 0.25f;
                float cmy = (sGT[0].y + sGT[1].y + sGT[2].y + sGT[3].y) * 0.25f;
                float ang[4]; int o4[4] = {0, 1, 2, 3};
                #pragma unroll
                for (int i = 0; i < 4; i++)
                    ang[i] = atan2f(__fsub_rn(sGT[i].y, cmy), __fsub_rn(sGT[i].x, cmx));
                for (int i = 1; i < 4; i++) {
                    int oi = o4[i]; float ki = ang[oi]; int jj = i - 1;
                    while (jj >= 0 && ang[o4[jj]] > ki) { o4[jj + 1] = o4[jj]; jj--; }
                    o4[jj + 1] = oi;
                }
                #pragma unroll
                for (int i = 0; i < 4; i++) sG[i] = sGT[o4[i]];
            }
            __syncwarp();
            int c = hull_warp_sorted(sP9, 9, sKeyA, sVa, lane);
            if (lane == 0) {
                s_apred = shoelace16(sVa, c);
                float sgt = 0.f;
                #pragma unroll
                for (int i = 0; i < 4; i++) {
                    int nx = (i + 1 < 4) ? i + 1 : 0;
                    sgt = __fadd_rn(sgt, cross_nf(sG[i].x, sG[i].y, sG[nx].x, sG[nx].y));
                }
                s_agt = 0.5f * fabsf(sgt);
            }
            for (int e = 0; e < 4; e++) clip_warp(sVa, c, sG[e], sG[(e + 1) & 3], lane, sScrA);
            if (lane == 0) s_aint = shoelace16(sVa, c);
        }
        __syncthreads();

        if (task && tid == 0) {
            float a_pred = s_apred, a_gt = s_agt, a_int = s_aint, a_hull = s_ahull;
            float uni = __fsub_rn(__fadd_rn(a_pred, a_gt), a_int);
            float iou = __fdiv_rn(a_int, __fadd_rn(uni, 1e-16f));
            float giou = __fsub_rn(iou, __fdiv_rn(__fsub_rn(a_hull, uni),
                                                  __fadd_rn(a_hull, 1e-16f)));
            float gl = __fsub_rn(1.0f, giou);

            float acc = 0.f;
            #pragma unroll
            for (int p = 0; p < 9; p++) {
                float mx = -f_inf();
                #pragma unroll
                for (int e = 0; e < 4; e++) {
                    float ex = __fsub_rn(sG[(e + 1) & 3].x, sG[e].x);
                    float ey = __fsub_rn(sG[(e + 1) & 3].y, sG[e].y);
                    float num = cross_nf(ex, ey, __fsub_rn(sP9[p].x, sG[e].x),
                                                 __fsub_rn(sP9[p].y, sG[e].y));
                    float sv = __fdiv_rn(num,
                        __fadd_rn(__fsqrt_rn(__fadd_rn(__fmul_rn(ex, ex),
                                                       __fmul_rn(ey, ey))), 1e-9f));
                    mx = fmaxf(mx, -sv);
                }
                acc = __fadd_rn(acc, fmaxf(mx, 0.f));
            }
            g_task_gl[s][m]  = (double)gl;
            g_task_oob[s][m] = (double)__fdiv_rn(acc, 9.0f);
        }
    }

    grid_barrier();   // --- barrier 3: tasks done ---

    // ---------------- Phase D (block 0): final reduce + combine + state restore ----------------
    if (bid == 0) {
        int c0 = g_pos_cnt[0], c1 = g_pos_cnt[1];
        for (int q = tid; q < 2 * KMAX; q += NTHR) {
            int s = q >> 6, m = q & 63;
            int cs = s ? c1 : c0;
            s_tgl[q] = (m < cs) ? g_task_gl[s][m]  : 0.0;
            s_tob[q] = (m < cs) ? g_task_oob[s][m] : 0.0;
        }
        double lpart = 0.0;
        for (int q = tid; q < NSM; q += NTHR) lpart += g_blk_lse[q];
        for (int o = 16; o; o >>= 1) lpart += __shfl_down_sync(0xffffffffu, lpart, o);
        if ((tid & 31) == 0) s_red[tid >> 5] = lpart;
        __syncthreads();
        if (tid == 0) {
            double lse = 0.0;
            for (int q = 0; q < NTHR / 32; q++) lse += s_red[q];
            double loc_i = 0.0, sc_i = 0.0, loc_r = 0.0, sc_r = 0.0;
            for (int m = 0; m < KMAX; m++) { loc_i += s_tgl[m];        sc_i += s_tob[m]; }
            for (int m = 0; m < KMAX; m++) { loc_r += s_tgl[KMAX + m]; sc_r += s_tob[KMAX + m]; }
            double cls_loss = (lse + g_corr_val) / (double)N;
            double ni = (double)max(c0, 1);
            double nr = (double)max(c1, 1);
            double loss = cls_loss
                        + 0.3  * (loc_i / ni)
                        + 1.0  * (loc_r / nr)
                        + 0.05 * (sc_i / ni)
                        + 0.1  * (sc_r / nr);
            out[0] = (float)loss;
        }
        // restore zero-init state for the next (identical) launch
        for (int q = tid; q < NB; q += NTHR) { g_best[0][q] = 0ull; g_best[1][q] = 0ull; }
    }
}

// ---------------- launch ----------------
extern "C" void kernel_launch(void* const* d_in, const int* in_sizes, int n_in,
                              void* d_out, int out_size)
{
    const float* rpi  = (const float*)d_in[0];
    const float* rpr  = (const float*)d_in[1];
    const float* cls  = (const float*)d_in[2];
    const float* pstr = (const float*)d_in[3];
    const float* gtb  = (const float*)d_in[4];
    const int*   glab = (const int*)d_in[5];
    float* out = (float*)d_out;

    int N = in_sizes[3];          // points_stride element count
    int K = in_sizes[5];          // gt_labels element count (=64)
    if (K > KMAX) K = KMAX;

    k_fused<<<NSM, NTHR>>>(rpi, rpr, cls, pstr, gtb, glab, N, K, out);
}

// round 7
// speedup vs baseline: 5.7039x; 1.1121x over previous
#include <cuda_runtime.h>
#include <math.h>
#include <stdint.h>

#define KMAX 64
#define BUF  16
#define NLVL 5          // levels 3..7
#define NB   (NLVL * KMAX)
#define NSM  148        // <= SM count on GB300 (152): all blocks co-resident
#define NTHR 1024
#define FULLM 0xffffffffu

// ---------------- device-global state (all zero-init; restored each launch) ----------------
__device__ unsigned g_bar_cnt;
__device__ unsigned g_bar_gen;                   // monotonic across launches
__device__ unsigned long long g_best[2][NB];     // INVERTED packed keys; 0 = empty (max-reduced)
__device__ int    g_pos_idx[2][KMAX];
__device__ int    g_pos_gt[2][KMAX];
__device__ int    g_pos_cnt[2];
__device__ double g_blk_lse[NSM];
__device__ double g_corr_val;
__device__ double g_task_gl[2][KMAX];
__device__ double g_task_oob[2][KMAX];

__device__ __forceinline__ float f_inf() { return __int_as_float(0x7f800000); }

// Non-FMA cross product: matches XLA's unfused mul/sub semantics exactly.
__device__ __forceinline__ float cross_nf(float ax, float ay, float bx, float by)
{
    return __fsub_rn(__fmul_rn(ax, by), __fmul_rn(ay, bx));
}

__device__ __forceinline__ void grid_barrier()
{
    __syncthreads();
    if (threadIdx.x == 0) {
        volatile unsigned* vgen = &g_bar_gen;
        unsigned gen = *vgen;
        __threadfence();
        unsigned prev = atomicAdd(&g_bar_cnt, 1u);
        if (prev == NSM - 1) {
            g_bar_cnt = 0;
            __threadfence();
            atomicAdd(&g_bar_gen, 1u);
        } else {
            while (*vgen == gen) { }
        }
    }
    __syncthreads();
}

// ---------------- geometry helpers ----------------
__device__ float shoelace16(const float2* V, int c)
{
    float s = 0.f;
    #pragma unroll
    for (int i = 0; i < BUF; i++) {
        if (i >= c) continue;
        int nxt = (i + 1 < c) ? i + 1 : 0;
        s = __fadd_rn(s, cross_nf(V[i].x, V[i].y, V[nxt].x, V[nxt].y));
    }
    return 0.5f * fabsf(s);
}

// membership of vertex i: one warp; lane j tests edge (i->j); any-over-j via ballot.
// min over k and any over j are exactly order-independent -> bit-identical to serial.
__device__ __forceinline__ int hull_member_warp(const float2* pts, int n, int i, int lane)
{
    bool flag = false;
    if (lane < n && lane != i) {
        float pix = pts[i].x, piy = pts[i].y;
        float dx = __fsub_rn(pts[lane].x, pix), dy = __fsub_rn(pts[lane].y, piy);
        float mn = f_inf();
        for (int k = 0; k < n; k++) {
            float cr = cross_nf(dx, dy, __fsub_rn(pts[k].x, pix), __fsub_rn(pts[k].y, piy));
            mn = fminf(mn, cr);
        }
        flag = (mn >= -1e-6f);
    }
    return __ballot_sync(FULLM, flag) != 0;
}

// finish a hull: centroid over members (ascending-order float sums = reference order),
// angle keys, warp-parallel STABLE rank sort (== jnp.argsort semantics), emit sV[BUF].
__device__ int hull_finish_warp(const float2* pts, int n, const int* hflag,
                                float* skey, float2* sV, int lane)
{
    bool hf = (lane < n) ? (hflag[lane] != 0) : false;
    unsigned mask = __ballot_sync(FULLM, hf);
    int cnt = __popc(mask);
    float sx = 0.f, sy = 0.f;
    for (int i = 0; i < n; i++)
        if ((mask >> i) & 1) { sx = __fadd_rn(sx, pts[i].x); sy = __fadd_rn(sy, pts[i].y); }
    float cd = (float)(cnt > 0 ? cnt : 1);
    float cenx = __fdiv_rn(sx, cd), ceny = __fdiv_rn(sy, cd);
    if (lane < n)
        skey[lane] = hf ? atan2f(__fsub_rn(pts[lane].y, ceny), __fsub_rn(pts[lane].x, cenx))
                        : f_inf();
    __syncwarp();
    if (lane < n) {
        float ki = skey[lane];
        int r = 0;
        for (int j = 0; j < n; j++) {
            float kj = skey[j];
            r += (kj < ki) || (kj == ki && j < lane);   // stable rank
        }
        sV[r] = pts[lane];
    }
    if (lane >= n && lane < BUF) sV[lane] = make_float2(0.f, 0.f);
    __syncwarp();
    return cnt;
}

// warp-parallel Sutherland-Hodgman, per-element math identical to serial reference
__device__ void clip_warp(float2* V, int& c, float2 a, float2 b, int lane, float2* scratch)
{
    float ex = __fsub_rn(b.x, a.x), ey = __fsub_rn(b.y, a.y);
    int cc = c;
    bool active = (lane < BUF) && (lane < cc);
    int nxt = (lane + 1 < cc) ? lane + 1 : 0;
    float2 cur = active ? V[lane] : make_float2(0.f, 0.f);
    float2 nx  = active ? V[nxt]  : make_float2(0.f, 0.f);
    float s_cur = cross_nf(ex, ey, __fsub_rn(cur.x, a.x), __fsub_rn(cur.y, a.y));
    float s_nxt = cross_nf(ex, ey, __fsub_rn(nx.x,  a.x), __fsub_rn(nx.y,  a.y));
    bool in_cur = s_cur >= 0.f, in_nxt = s_nxt >= 0.f;
    float den = __fsub_rn(s_cur, s_nxt);
    float t = (fabsf(den) > 1e-9f) ? __fdiv_rn(s_cur, den) : 0.f;
    float2 ipt = make_float2(__fadd_rn(cur.x, __fmul_rn(t, __fsub_rn(nx.x, cur.x))),
                             __fadd_rn(cur.y, __fmul_rn(t, __fsub_rn(nx.y, cur.y))));
    bool f_int = active && (in_cur != in_nxt);
    bool f_nxt = active && in_nxt;
    unsigned bi = __ballot_sync(FULLM, f_int);
    unsigned bn = __ballot_sync(FULLM, f_nxt);
    unsigned below = (1u << lane) - 1u;
    int pos_i = __popc(bi & below) + __popc(bn & below);
    int pos_n = pos_i + (f_int ? 1 : 0);
    int nc = __popc(bi) + __popc(bn);
    __syncwarp();
    if (f_int && pos_i < BUF) scratch[pos_i] = ipt;
    if (f_nxt && pos_n < BUF) scratch[pos_n] = nx;
    __syncwarp();
    if (lane < BUF) V[lane] = (lane < nc) ? scratch[lane] : make_float2(0.f, 0.f);
    __syncwarp();
    c = nc;
}

// ---------------- the one fused kernel ----------------
__global__ void __launch_bounds__(NTHR) k_fused(
    const float* __restrict__ rpi, const float* __restrict__ rpr,
    const float* __restrict__ cls, const float* __restrict__ pstr,
    const float* __restrict__ gtb, const int* __restrict__ glab,
    int N, int K, float* __restrict__ out)
{
    __shared__ float  s_cx[KMAX], s_cy[KMAX], s_rw[KMAX], s_rh[KMAX];
    __shared__ int    s_lvl[KMAX];
    __shared__ float4 s_bkt[NB];
    __shared__ int    s_k2b[KMAX];
    __shared__ int    s_cnt[NLVL];
    __shared__ unsigned long long sb0[NB], sb1[NB];
    __shared__ double s_red[32];
    // scan
    __shared__ unsigned long long s_cmp[KMAX];
    __shared__ int s_j[KMAX];
    __shared__ int s_lead[KMAX];
    __shared__ int s_mcnt[2];
    // geom
    __shared__ float2 sP9[9];
    __shared__ float2 sGT[4];
    __shared__ float2 sG[4];
    __shared__ float2 sPtsB[13];
    __shared__ int    sHa[9], sHb[13];
    __shared__ float2 sVa[BUF], sVb[BUF];
    __shared__ float2 sScrA[BUF];
    __shared__ float  sKeyA[13], sKeyB[13], sKeyG[4];
    __shared__ float  s_apred, s_agt, s_aint, s_ahull, s_oob;
    // final
    __shared__ double s_tgl[2 * KMAX], s_tob[2 * KMAX];

    const int tid  = threadIdx.x;
    const int bid  = blockIdx.x;
    const int lane = tid & 31;
    const int w    = tid >> 5;

    // ---------------- Phase A: prep + assign + lse ----------------
    for (int q = tid; q < NB; q += NTHR) { sb0[q] = 0ull; sb1[q] = 0ull; }
    if (tid < K) {
        const float* r = gtb + 8 * tid;
        float xmn = fminf(fminf(r[0], r[2]), fminf(r[4], r[6]));
        float xmx = fmaxf(fmaxf(r[0], r[2]), fmaxf(r[4], r[6]));
        float ymn = fminf(fminf(r[1], r[3]), fminf(r[5], r[7]));
        float ymx = fmaxf(fmaxf(r[1], r[3]), fmaxf(r[5], r[7]));
        float ww = fmaxf(__fsub_rn(xmx, xmn), 1e-6f);
        float hh = fmaxf(__fsub_rn(ymx, ymn), 1e-6f);
        s_cx[tid] = __fmul_rn(__fadd_rn(xmn, xmx), 0.5f);
        s_cy[tid] = __fmul_rn(__fadd_rn(ymn, ymx), 0.5f);
        s_rw[tid] = __fdiv_rn(1.0f, ww);
        s_rh[tid] = __fdiv_rn(1.0f, hh);
        float lv = __fmul_rn(__fadd_rn(log2f(__fdiv_rn(ww, 4.0f)),
                                       log2f(__fdiv_rn(hh, 4.0f))), 0.5f);
        int lvl = (int)lv;
        s_lvl[tid] = max(3, min(7, lvl));
    }
    __syncthreads();
    if (tid == 0) {                                  // serial bucket build, ascending k
        int cnt[NLVL];
        #pragma unroll
        for (int l = 0; l < NLVL; l++) cnt[l] = 0;
        for (int q = 0; q < K; q++) {
            int li = s_lvl[q] - 3;
            int slot = li * KMAX + cnt[li];
            s_bkt[slot] = make_float4(s_cx[q], s_cy[q], s_rw[q], s_rh[q]);
            s_k2b[q] = slot;
            cnt[li]++;
        }
        #pragma unroll
        for (int l = 0; l < NLVL; l++) s_cnt[l] = cnt[l];
    }
    __syncthreads();

    double lterm = 0.0;
    for (int n = bid * NTHR + tid; n - tid < N; n += NSM * NTHR) {
        bool act = (n < N);
        int li = 0;
        float2 pi = make_float2(0.f, 0.f), pr = make_float2(0.f, 0.f);
        if (act) {
            li = (31 - __clz((int)pstr[n])) - 3;
            pi = __ldg((const float2*)(rpi + (size_t)n * 18 + 8));
            pr = __ldg((const float2*)(rpr + (size_t)n * 18 + 8));
        }
        unsigned un = (unsigned)n;
        unsigned actmask = __ballot_sync(FULLM, act);
        if (actmask) {
            int src = __ffs(actmask) - 1;
            int uli = __shfl_sync(FULLM, li, src);
            bool uniform = __all_sync(FULLM, !act || (li == uli));
            if (uniform) {
                // warp-aggregated: shfl-max reduce each slot key, single atomic by lane 0
                int cnt = s_cnt[uli], base = uli * KMAX;
                for (int m = 0; m < cnt; m++) {
                    int slot = base + m;
                    float4 gq = s_bkt[slot];
                    unsigned long long ki = 0ull, kr = 0ull;
                    if (act) {
                        float dxi = __fmul_rn(__fsub_rn(pi.x, gq.x), gq.z);
                        float dyi = __fmul_rn(__fsub_rn(pi.y, gq.y), gq.w);
                        float ddi = __fadd_rn(__fmul_rn(dxi, dxi), __fmul_rn(dyi, dyi));
                        ki = ~(((unsigned long long)__float_as_uint(ddi) << 32) | un);
                        float dxr = __fmul_rn(__fsub_rn(pr.x, gq.x), gq.z);
                        float dyr = __fmul_rn(__fsub_rn(pr.y, gq.y), gq.w);
                        float ddr = __fadd_rn(__fmul_rn(dxr, dxr), __fmul_rn(dyr, dyr));
                        kr = ~(((unsigned long long)__float_as_uint(ddr) << 32) | un);
                    }
                    #pragma unroll
                    for (int o = 16; o; o >>= 1) {
                        unsigned long long ti = __shfl_down_sync(FULLM, ki, o);
                        unsigned long long tr = __shfl_down_sync(FULLM, kr, o);
                        if (ti > ki) ki = ti;
                        if (tr > kr) kr = tr;
                    }
                    if (lane == 0) {
                        if (ki > sb0[slot]) atomicMax(&sb0[slot], ki);
                        if (kr > sb1[slot]) atomicMax(&sb1[slot], kr);
                    }
                }
            } else if (act) {
                int cnt = s_cnt[li], base = li * KMAX;
                for (int m = 0; m < cnt; m++) {
                    int slot = base + m;
                    float4 gq = s_bkt[slot];
                    float dxi = __fmul_rn(__fsub_rn(pi.x, gq.x), gq.z);
                    float dyi = __fmul_rn(__fsub_rn(pi.y, gq.y), gq.w);
                    float ddi = __fadd_rn(__fmul_rn(dxi, dxi), __fmul_rn(dyi, dyi));
                    unsigned long long ki = ~(((unsigned long long)__float_as_uint(ddi) << 32) | un);
                    if (ki > sb0[slot]) atomicMax(&sb0[slot], ki);
                    float dxr = __fmul_rn(__fsub_rn(pr.x, gq.x), gq.z);
                    float dyr = __fmul_rn(__fsub_rn(pr.y, gq.y), gq.w);
                    float ddr = __fadd_rn(__fmul_rn(dxr, dxr), __fmul_rn(dyr, dyr));
                    unsigned long long kr = ~(((unsigned long long)__float_as_uint(ddr) << 32) | un);
                    if (kr > sb1[slot]) atomicMax(&sb1[slot], kr);
                }
            }
        }
        if (act) {
            const float4* c4 = (const float4*)(cls + (size_t)n * 16);
            float v[16];
            #pragma unroll
            for (int j = 0; j < 4; j++) {
                float4 f = __ldg(c4 + j);
                v[4 * j] = f.x; v[4 * j + 1] = f.y; v[4 * j + 2] = f.z; v[4 * j + 3] = f.w;
            }
            float mm = v[0];
            #pragma unroll
            for (int j = 1; j < 16; j++) mm = fmaxf(mm, v[j]);
            float ss = 0.f;
            #pragma unroll
            for (int j = 0; j < 16; j++) ss += __expf(v[j] - mm);
            lterm += (double)((mm + __logf(ss)) - v[0]);
        }
    }
    for (int o = 16; o; o >>= 1) lterm += __shfl_down_sync(FULLM, lterm, o);
    if (lane == 0) s_red[w] = lterm;
    __syncthreads();
    if (tid == 0) {
        double bs = 0.0;
        for (int q = 0; q < NTHR / 32; q++) bs += s_red[q];
        g_blk_lse[bid] = bs;
    }
    for (int q = tid; q < NB; q += NTHR) {
        if (sb0[q]) atomicMax(&g_best[0][q], sb0[q]);
        if (sb1[q]) atomicMax(&g_best[1][q], sb1[q]);
    }

    grid_barrier();   // --- barrier 1: assign complete ---

    // ---------------- Phase B (block 0): scan replay + cls correction ----------------
    if (bid == 0) {
        for (int s = 0; s < 2; s++) {
            if (tid < KMAX) {
                unsigned long long v = (tid < K) ? g_best[s][s_k2b[tid]] : 0ull;
                bool valid = (v != 0ull);
                unsigned long long pk = ~v;          // (md_bits<<32)|point_idx
                s_j[tid]   = valid ? (int)(unsigned)(pk & 0xffffffffu) : (-1 - tid);
                s_cmp[tid] = valid ? (((pk >> 32) << 32) | (unsigned)tid) : ~0ull;
            }
            __syncthreads();
            if (tid < KMAX) {
                int j = s_j[tid];
                bool lead = (j >= 0);
                if (lead)
                    for (int e = 0; e < tid; e++)
                        if (s_j[e] == j) { lead = false; break; }
                s_lead[tid] = lead ? 1 : 0;
            }
            __syncthreads();
            if (tid < K && s_lead[tid]) {
                int j = s_j[tid];
                unsigned long long best = s_cmp[tid];
                for (int e = 0; e < K; e++)
                    if (s_j[e] == j && s_cmp[e] < best) best = s_cmp[e];
                int pos = 0;
                for (int e = 0; e < tid; e++) pos += s_lead[e];
                g_pos_idx[s][pos] = j;
                g_pos_gt[s][pos]  = (int)(unsigned)(best & 0xffffffffu);
            }
            __syncthreads();
            if (tid == 0) {
                int m = 0;
                for (int e = 0; e < K; e++) m += s_lead[e];
                g_pos_cnt[s] = m;
                s_mcnt[s] = m;
            }
            __syncthreads();
        }
        double part = 0.0;
        if (tid < s_mcnt[1]) {
            int j   = g_pos_idx[1][tid];
            int lab = glab[g_pos_gt[1][tid]];
            part = (double)cls[(size_t)j * 16 + 0] - (double)cls[(size_t)j * 16 + lab];
        }
        for (int o = 16; o; o >>= 1) part += __shfl_down_sync(FULLM, part, o);
        if (lane == 0) s_red[w] = part;
        __syncthreads();
        if (tid == 0) {
            double cs = 0.0;
            for (int q = 0; q < NTHR / 32; q++) cs += s_red[q];
            g_corr_val = cs;
        }
    }

    grid_barrier();   // --- barrier 2: positives ready ---

    // ---------------- Phase C: geometry, one task per block, many warps ----------------
    {
        int s = (bid >= KMAX) ? 1 : 0;
        int m = bid - s * KMAX;
        bool task = (bid < 2 * KMAX) && (m < g_pos_cnt[s]);

        if (task) {
            const float* rp  = s ? rpr : rpi;
            int j  = g_pos_idx[s][m];
            int gi = g_pos_gt[s][m];
            const float* g8  = gtb + 8 * gi;
            const float* p18 = rp + (size_t)j * 18;
            if (tid < 4) {
                float2 c = make_float2(g8[2 * tid], g8[2 * tid + 1]);
                sGT[tid] = c;
                sPtsB[tid] = c;
            }
            if (tid >= 4 && tid < 13) {
                float2 c = make_float2(p18[2 * (tid - 4)], p18[2 * (tid - 4) + 1]);
                sP9[tid - 4] = c;
                sPtsB[tid] = c;
            }
        }
        __syncthreads();

        if (task) {
            // membership: warps 0-12 -> big hull vertex w; warps 16-24 -> pred vertex w-16
            if (w < 13) {
                int h = hull_member_warp(sPtsB, 13, w, lane);
                if (lane == 0) sHb[w] = h;
            } else if (w >= 16 && w < 25) {
                int h = hull_member_warp(sP9, 9, w - 16, lane);
                if (lane == 0) sHa[w - 16] = h;
            } else if (w == 13) {
                // gt CCW ordering by angle around mean, stable rank (== argsort)
                if (lane < 4) {
                    float cmx = (sGT[0].x + sGT[1].x + sGT[2].x + sGT[3].x) * 0.25f;
                    float cmy = (sGT[0].y + sGT[1].y + sGT[2].y + sGT[3].y) * 0.25f;
                    sKeyG[lane] = atan2f(__fsub_rn(sGT[lane].y, cmy),
                                         __fsub_rn(sGT[lane].x, cmx));
                }
                __syncwarp();
                if (lane < 4) {
                    float ki = sKeyG[lane];
                    int r = 0;
                    #pragma unroll
                    for (int j = 0; j < 4; j++) {
                        float kj = sKeyG[j];
                        r += (kj < ki) || (kj == ki && j < lane);
                    }
                    sG[r] = sGT[lane];
                }
            }
        }
        __syncthreads();

        if (task) {
            if (w == 0) {
                // pred hull finish -> clip -> a_int
                int c = hull_finish_warp(sP9, 9, sHa, sKeyA, sVa, lane);
                if (lane == 0) {
                    s_apred = shoelace16(sVa, c);
                    float sgt = 0.f;
                    #pragma unroll
                    for (int i = 0; i < 4; i++) {
                        int nx = (i + 1 < 4) ? i + 1 : 0;
                        sgt = __fadd_rn(sgt, cross_nf(sG[i].x, sG[i].y, sG[nx].x, sG[nx].y));
                    }
                    s_agt = 0.5f * fabsf(sgt);
                }
                for (int e = 0; e < 4; e++) clip_warp(sVa, c, sG[e], sG[(e + 1) & 3], lane, sScrA);
                if (lane == 0) s_aint = shoelace16(sVa, c);
            } else if (w == 1) {
                int ch = hull_finish_warp(sPtsB, 13, sHb, sKeyB, sVb, lane);
                if (lane == 0) s_ahull = shoelace16(sVb, ch);
            } else if (w == 2) {
                // oob: lane p<9 computes its max term; lane 0 sums ascending (ref order)
                float val = 0.f;
                if (lane < 9) {
                    float mx = -f_inf();
                    #pragma unroll
                    for (int e = 0; e < 4; e++) {
                        float ex = __fsub_rn(sG[(e + 1) & 3].x, sG[e].x);
                        float ey = __fsub_rn(sG[(e + 1) & 3].y, sG[e].y);
                        float num = cross_nf(ex, ey, __fsub_rn(sP9[lane].x, sG[e].x),
                                                     __fsub_rn(sP9[lane].y, sG[e].y));
                        float sv = __fdiv_rn(num,
                            __fadd_rn(__fsqrt_rn(__fadd_rn(__fmul_rn(ex, ex),
                                                           __fmul_rn(ey, ey))), 1e-9f));
                        mx = fmaxf(mx, -sv);
                    }
                    val = fmaxf(mx, 0.f);
                }
                float acc = 0.f;
                #pragma unroll
                for (int p = 0; p < 9; p++) {
                    float vp = __shfl_sync(FULLM, val, p);
                    acc = __fadd_rn(acc, vp);
                }
                if (lane == 0) s_oob = __fdiv_rn(acc, 9.0f);
            }
        }
        __syncthreads();

        if (task && tid == 0) {
            float uni = __fsub_rn(__fadd_rn(s_apred, s_agt), s_aint);
            float iou = __fdiv_rn(s_aint, __fadd_rn(uni, 1e-16f));
            float giou = __fsub_rn(iou, __fdiv_rn(__fsub_rn(s_ahull, uni),
                                                  __fadd_rn(s_ahull, 1e-16f)));
            g_task_gl[s][m]  = (double)__fsub_rn(1.0f, giou);
            g_task_oob[s][m] = (double)s_oob;
        }
    }

    grid_barrier();   // --- barrier 3: tasks done ---

    // ---------------- Phase D (block 0): final reduce + combine + state restore ----------------
    if (bid == 0) {
        int c0 = g_pos_cnt[0], c1 = g_pos_cnt[1];
        for (int q = tid; q < 2 * KMAX; q += NTHR) {
            int s = q >> 6, mm = q & 63;
            int cs = s ? c1 : c0;
            s_tgl[q] = (mm < cs) ? g_task_gl[s][mm]  : 0.0;
            s_tob[q] = (mm < cs) ? g_task_oob[s][mm] : 0.0;
        }
        double lpart = 0.0;
        for (int q = tid; q < NSM; q += NTHR) lpart += g_blk_lse[q];
        for (int o = 16; o; o >>= 1) lpart += __shfl_down_sync(FULLM, lpart, o);
        if (lane == 0) s_red[w] = lpart;
        __syncthreads();
        if (tid == 0) {
            double lse = 0.0;
            for (int q = 0; q < NTHR / 32; q++) lse += s_red[q];
            double loc_i = 0.0, sc_i = 0.0, loc_r = 0.0, sc_r = 0.0;
            for (int mm = 0; mm < KMAX; mm++) { loc_i += s_tgl[mm];        sc_i += s_tob[mm]; }
            for (int mm = 0; mm < KMAX; mm++) { loc_r += s_tgl[KMAX + mm]; sc_r += s_tob[KMAX + mm]; }
            double cls_loss = (lse + g_corr_val) / (double)N;
            double ni = (double)max(c0, 1);
            double nr = (double)max(c1, 1);
            double loss = cls_loss
                        + 0.3  * (loc_i / ni)
                        + 1.0  * (loc_r / nr)
                        + 0.05 * (sc_i / ni)
                        + 0.1  * (sc_r / nr);
            out[0] = (float)loss;
        }
        for (int q = tid; q < NB; q += NTHR) { g_best[0][q] = 0ull; g_best[1][q] = 0ull; }
    }
}

// ---------------- launch ----------------
extern "C" void kernel_launch(void* const* d_in, const int* in_sizes, int n_in,
                              void* d_out, int out_size)
{
    const float* rpi  = (const float*)d_in[0];
    const float* rpr  = (const float*)d_in[1];
    const float* cls  = (const float*)d_in[2];
    const float* pstr = (const float*)d_in[3];
    const float* gtb  = (const float*)d_in[4];
    const int*   glab = (const int*)d_in[5];
    float* out = (float*)d_out;

    int N = in_sizes[3];          // points_stride element count
    int K = in_sizes[5];          // gt_labels element count (=64)
    if (K > KMAX) K = KMAX;

    k_fused<<<NSM, NTHR>>>(rpi, rpr, cls, pstr, gtb, glab, N, K, out);
}

// round 8
// speedup vs baseline: 6.5453x; 1.1475x over previous
#include <cuda_runtime.h>
#include <math.h>
#include <stdint.h>

#define KMAX 64
#define BUF  16
#define NLVL 5          // levels 3..7
#define NB   (NLVL * KMAX)
#define NSM  148        // <= SM count on GB300 (152): all blocks co-resident
#define NTHR 1024
#define FULLM 0xffffffffu

// ---------------- device-global state (zero-init; restored by the last block) ----------------
__device__ unsigned g_bar_cnt;
__device__ unsigned g_bar_gen;                   // monotonic across launches
__device__ unsigned g_ticket;                    // completion counter (reset each launch)
__device__ unsigned long long g_best[2][NB];     // INVERTED packed keys; 0 = empty (max-reduced)
__device__ int    g_cnt01[2];
__device__ double g_blk_lse[NSM];
__device__ double g_corr_val;
__device__ double g_task_gl[2][KMAX];
__device__ double g_task_oob[2][KMAX];

__device__ __forceinline__ float f_inf() { return __int_as_float(0x7f800000); }

// Non-FMA cross product: matches XLA's unfused mul/sub semantics exactly.
__device__ __forceinline__ float cross_nf(float ax, float ay, float bx, float by)
{
    return __fsub_rn(__fmul_rn(ax, by), __fmul_rn(ay, bx));
}

__device__ __forceinline__ void grid_barrier()
{
    __syncthreads();
    if (threadIdx.x == 0) {
        volatile unsigned* vgen = &g_bar_gen;
        unsigned gen = *vgen;
        __threadfence();
        unsigned prev = atomicAdd(&g_bar_cnt, 1u);
        if (prev == NSM - 1) {
            g_bar_cnt = 0;
            __threadfence();
            atomicAdd(&g_bar_gen, 1u);
        } else {
            while (*vgen == gen) { }
        }
    }
    __syncthreads();
}

// ---------------- geometry helpers (bit-identical to prior passing rounds) ----------------
__device__ float shoelace16(const float2* V, int c)
{
    float s = 0.f;
    #pragma unroll
    for (int i = 0; i < BUF; i++) {
        if (i >= c) continue;
        int nxt = (i + 1 < c) ? i + 1 : 0;
        s = __fadd_rn(s, cross_nf(V[i].x, V[i].y, V[nxt].x, V[nxt].y));
    }
    return 0.5f * fabsf(s);
}

__device__ __forceinline__ int hull_member_warp(const float2* pts, int n, int i, int lane)
{
    bool flag = false;
    if (lane < n && lane != i) {
        float pix = pts[i].x, piy = pts[i].y;
        float dx = __fsub_rn(pts[lane].x, pix), dy = __fsub_rn(pts[lane].y, piy);
        float mn = f_inf();
        for (int k = 0; k < n; k++) {
            float cr = cross_nf(dx, dy, __fsub_rn(pts[k].x, pix), __fsub_rn(pts[k].y, piy));
            mn = fminf(mn, cr);
        }
        flag = (mn >= -1e-6f);
    }
    return __ballot_sync(FULLM, flag) != 0;
}

__device__ int hull_finish_warp(const float2* pts, int n, const int* hflag,
                                float* skey, float2* sV, int lane)
{
    bool hf = (lane < n) ? (hflag[lane] != 0) : false;
    unsigned mask = __ballot_sync(FULLM, hf);
    int cnt = __popc(mask);
    float sx = 0.f, sy = 0.f;
    for (int i = 0; i < n; i++)
        if ((mask >> i) & 1) { sx = __fadd_rn(sx, pts[i].x); sy = __fadd_rn(sy, pts[i].y); }
    float cd = (float)(cnt > 0 ? cnt : 1);
    float cenx = __fdiv_rn(sx, cd), ceny = __fdiv_rn(sy, cd);
    if (lane < n)
        skey[lane] = hf ? atan2f(__fsub_rn(pts[lane].y, ceny), __fsub_rn(pts[lane].x, cenx))
                        : f_inf();
    __syncwarp();
    if (lane < n) {
        float ki = skey[lane];
        int r = 0;
        for (int j = 0; j < n; j++) {
            float kj = skey[j];
            r += (kj < ki) || (kj == ki && j < lane);   // stable rank == argsort
        }
        sV[r] = pts[lane];
    }
    if (lane >= n && lane < BUF) sV[lane] = make_float2(0.f, 0.f);
    __syncwarp();
    return cnt;
}

__device__ void clip_warp(float2* V, int& c, float2 a, float2 b, int lane, float2* scratch)
{
    float ex = __fsub_rn(b.x, a.x), ey = __fsub_rn(b.y, a.y);
    int cc = c;
    bool active = (lane < BUF) && (lane < cc);
    int nxt = (lane + 1 < cc) ? lane + 1 : 0;
    float2 cur = active ? V[lane] : make_float2(0.f, 0.f);
    float2 nx  = active ? V[nxt]  : make_float2(0.f, 0.f);
    float s_cur = cross_nf(ex, ey, __fsub_rn(cur.x, a.x), __fsub_rn(cur.y, a.y));
    float s_nxt = cross_nf(ex, ey, __fsub_rn(nx.x,  a.x), __fsub_rn(nx.y,  a.y));
    bool in_cur = s_cur >= 0.f, in_nxt = s_nxt >= 0.f;
    float den = __fsub_rn(s_cur, s_nxt);
    float t = (fabsf(den) > 1e-9f) ? __fdiv_rn(s_cur, den) : 0.f;
    float2 ipt = make_float2(__fadd_rn(cur.x, __fmul_rn(t, __fsub_rn(nx.x, cur.x))),
                             __fadd_rn(cur.y, __fmul_rn(t, __fsub_rn(nx.y, cur.y))));
    bool f_int = active && (in_cur != in_nxt);
    bool f_nxt = active && in_nxt;
    unsigned bi = __ballot_sync(FULLM, f_int);
    unsigned bn = __ballot_sync(FULLM, f_nxt);
    unsigned below = (1u << lane) - 1u;
    int pos_i = __popc(bi & below) + __popc(bn & below);
    int pos_n = pos_i + (f_int ? 1 : 0);
    int nc = __popc(bi) + __popc(bn);
    __syncwarp();
    if (f_int && pos_i < BUF) scratch[pos_i] = ipt;
    if (f_nxt && pos_n < BUF) scratch[pos_n] = nx;
    __syncwarp();
    if (lane < BUF) V[lane] = (lane < nc) ? scratch[lane] : make_float2(0.f, 0.f);
    __syncwarp();
    c = nc;
}

// ---------------- the one fused kernel ----------------
__global__ void __launch_bounds__(NTHR) k_fused(
    const float* __restrict__ rpi, const float* __restrict__ rpr,
    const float* __restrict__ cls, const float* __restrict__ pstr,
    const float* __restrict__ gtb, const int* __restrict__ glab,
    int N, int K, float* __restrict__ out)
{
    __shared__ float  s_cx[KMAX], s_cy[KMAX], s_rw[KMAX], s_rh[KMAX];
    __shared__ int    s_lvl[KMAX];
    __shared__ float4 s_bkt[NB];
    __shared__ int    s_k2b[KMAX];
    __shared__ int    s_cnt[NLVL];
    __shared__ unsigned long long sb0[NB], sb1[NB];
    __shared__ double s_red[32];
    // replay (per-block, own stage)
    __shared__ unsigned long long s_cmp[KMAX];
    __shared__ int s_j[KMAX];
    __shared__ int s_lead[KMAX];
    __shared__ int s_pidx[KMAX], s_pgt[KMAX];
    __shared__ int s_npos;
    // geom
    __shared__ float2 sP9[9];
    __shared__ float2 sGT[4];
    __shared__ float2 sG[4];
    __shared__ float2 sPtsB[13];
    __shared__ int    sHa[9], sHb[13];
    __shared__ float2 sVa[BUF], sVb[BUF];
    __shared__ float2 sScrA[BUF];
    __shared__ float  sKeyA[13], sKeyB[13], sKeyG[4];
    __shared__ float  s_apred, s_agt, s_aint, s_ahull, s_oob;
    // final
    __shared__ double s_tgl[2 * KMAX], s_tob[2 * KMAX];
    __shared__ double s_lse[NSM];
    __shared__ int    s_last;

    const int tid  = threadIdx.x;
    const int bid  = blockIdx.x;
    const int lane = tid & 31;
    const int w    = tid >> 5;

    // ---------------- Phase A: prep + assign + lse ----------------
    for (int q = tid; q < NB; q += NTHR) { sb0[q] = 0ull; sb1[q] = 0ull; }
    if (tid < K) {
        const float* r = gtb + 8 * tid;
        float xmn = fminf(fminf(r[0], r[2]), fminf(r[4], r[6]));
        float xmx = fmaxf(fmaxf(r[0], r[2]), fmaxf(r[4], r[6]));
        float ymn = fminf(fminf(r[1], r[3]), fminf(r[5], r[7]));
        float ymx = fmaxf(fmaxf(r[1], r[3]), fmaxf(r[5], r[7]));
        float ww = fmaxf(__fsub_rn(xmx, xmn), 1e-6f);
        float hh = fmaxf(__fsub_rn(ymx, ymn), 1e-6f);
        s_cx[tid] = __fmul_rn(__fadd_rn(xmn, xmx), 0.5f);
        s_cy[tid] = __fmul_rn(__fadd_rn(ymn, ymx), 0.5f);
        s_rw[tid] = __fdiv_rn(1.0f, ww);
        s_rh[tid] = __fdiv_rn(1.0f, hh);
        float lv = __fmul_rn(__fadd_rn(log2f(__fdiv_rn(ww, 4.0f)),
                                       log2f(__fdiv_rn(hh, 4.0f))), 0.5f);
        int lvl = (int)lv;
        s_lvl[tid] = max(3, min(7, lvl));
    }
    __syncthreads();
    if (tid == 0) {                                  // serial bucket build, ascending k
        int cnt[NLVL];
        #pragma unroll
        for (int l = 0; l < NLVL; l++) cnt[l] = 0;
        for (int q = 0; q < K; q++) {
            int li = s_lvl[q] - 3;
            int slot = li * KMAX + cnt[li];
            s_bkt[slot] = make_float4(s_cx[q], s_cy[q], s_rw[q], s_rh[q]);
            s_k2b[q] = slot;
            cnt[li]++;
        }
        #pragma unroll
        for (int l = 0; l < NLVL; l++) s_cnt[l] = cnt[l];
    }
    __syncthreads();

    double lterm = 0.0;
    for (int n = bid * NTHR + tid; n - tid < N; n += NSM * NTHR) {
        bool act = (n < N);
        int li = 0;
        float2 pi = make_float2(0.f, 0.f), pr = make_float2(0.f, 0.f);
        if (act) {
            li = (31 - __clz((int)pstr[n])) - 3;
            pi = __ldg((const float2*)(rpi + (size_t)n * 18 + 8));
            pr = __ldg((const float2*)(rpr + (size_t)n * 18 + 8));
        }
        unsigned un = (unsigned)n;
        unsigned actmask = __ballot_sync(FULLM, act);
        if (actmask) {
            int src = __ffs(actmask) - 1;
            int uli = __shfl_sync(FULLM, li, src);
            bool uniform = __all_sync(FULLM, !act || (li == uli));
            if (uniform) {
                int cnt = s_cnt[uli], base = uli * KMAX;
                for (int m = 0; m < cnt; m++) {
                    int slot = base + m;
                    float4 gq = s_bkt[slot];
                    unsigned long long ki = 0ull, kr = 0ull;
                    if (act) {
                        float dxi = __fmul_rn(__fsub_rn(pi.x, gq.x), gq.z);
                        float dyi = __fmul_rn(__fsub_rn(pi.y, gq.y), gq.w);
                        float ddi = __fadd_rn(__fmul_rn(dxi, dxi), __fmul_rn(dyi, dyi));
                        ki = ~(((unsigned long long)__float_as_uint(ddi) << 32) | un);
                        float dxr = __fmul_rn(__fsub_rn(pr.x, gq.x), gq.z);
                        float dyr = __fmul_rn(__fsub_rn(pr.y, gq.y), gq.w);
                        float ddr = __fadd_rn(__fmul_rn(dxr, dxr), __fmul_rn(dyr, dyr));
                        kr = ~(((unsigned long long)__float_as_uint(ddr) << 32) | un);
                    }
                    #pragma unroll
                    for (int o = 16; o; o >>= 1) {
                        unsigned long long ti = __shfl_down_sync(FULLM, ki, o);
                        unsigned long long tr = __shfl_down_sync(FULLM, kr, o);
                        if (ti > ki) ki = ti;
                        if (tr > kr) kr = tr;
                    }
                    if (lane == 0) {
                        if (ki > sb0[slot]) atomicMax(&sb0[slot], ki);
                        if (kr > sb1[slot]) atomicMax(&sb1[slot], kr);
                    }
                }
            } else if (act) {
                int cnt = s_cnt[li], base = li * KMAX;
                for (int m = 0; m < cnt; m++) {
                    int slot = base + m;
                    float4 gq = s_bkt[slot];
                    float dxi = __fmul_rn(__fsub_rn(pi.x, gq.x), gq.z);
                    float dyi = __fmul_rn(__fsub_rn(pi.y, gq.y), gq.w);
                    float ddi = __fadd_rn(__fmul_rn(dxi, dxi), __fmul_rn(dyi, dyi));
                    unsigned long long ki = ~(((unsigned long long)__float_as_uint(ddi) << 32) | un);
                    if (ki > sb0[slot]) atomicMax(&sb0[slot], ki);
                    float dxr = __fmul_rn(__fsub_rn(pr.x, gq.x), gq.z);
                    float dyr = __fmul_rn(__fsub_rn(pr.y, gq.y), gq.w);
                    float ddr = __fadd_rn(__fmul_rn(dxr, dxr), __fmul_rn(dyr, dyr));
                    unsigned long long kr = ~(((unsigned long long)__float_as_uint(ddr) << 32) | un);
                    if (kr > sb1[slot]) atomicMax(&sb1[slot], kr);
                }
            }
        }
        if (act) {
            const float4* c4 = (const float4*)(cls + (size_t)n * 16);
            float v[16];
            #pragma unroll
            for (int j = 0; j < 4; j++) {
                float4 f = __ldg(c4 + j);
                v[4 * j] = f.x; v[4 * j + 1] = f.y; v[4 * j + 2] = f.z; v[4 * j + 3] = f.w;
            }
            float mm = v[0];
            #pragma unroll
            for (int j = 1; j < 16; j++) mm = fmaxf(mm, v[j]);
            float ss = 0.f;
            #pragma unroll
            for (int j = 0; j < 16; j++) ss += __expf(v[j] - mm);
            lterm += (double)((mm + __logf(ss)) - v[0]);
        }
    }
    for (int o = 16; o; o >>= 1) lterm += __shfl_down_sync(FULLM, lterm, o);
    if (lane == 0) s_red[w] = lterm;
    __syncthreads();
    if (tid == 0) {
        double bs = 0.0;
        for (int q = 0; q < NTHR / 32; q++) bs += s_red[q];
        g_blk_lse[bid] = bs;
    }
    for (int q = tid; q < NB; q += NTHR) {
        if (sb0[q]) atomicMax(&g_best[0][q], sb0[q]);
        if (sb1[q]) atomicMax(&g_best[1][q], sb1[q]);
    }

    grid_barrier();   // --- the ONLY grid barrier: assign complete ---

    // ---------------- Phase B+C (blocks 0..127): per-block replay of OWN stage + task ----------------
    if (bid < 2 * KMAX) {
        int s = (bid >= KMAX) ? 1 : 0;
        int m = bid - s * KMAX;

        // replay stage s (order-independent reformulation, validated rounds 6-7)
        if (tid < KMAX) {
            unsigned long long v = (tid < K) ? __ldcg(&g_best[s][s_k2b[tid]]) : 0ull;
            bool valid = (v != 0ull);
            unsigned long long pk = ~v;              // (md_bits<<32)|point_idx
            s_j[tid]   = valid ? (int)(unsigned)(pk & 0xffffffffu) : (-1 - tid);
            s_cmp[tid] = valid ? (((pk >> 32) << 32) | (unsigned)tid) : ~0ull;
        }
        __syncthreads();
        if (tid < KMAX) {
            int j = s_j[tid];
            bool lead = (j >= 0);
            if (lead)
                for (int e = 0; e < tid; e++)
                    if (s_j[e] == j) { lead = false; break; }
            s_lead[tid] = lead ? 1 : 0;
        }
        __syncthreads();
        if (tid < K && s_lead[tid]) {
            int j = s_j[tid];
            unsigned long long best = s_cmp[tid];
            for (int e = 0; e < K; e++)
                if (s_j[e] == j && s_cmp[e] < best) best = s_cmp[e];
            int pos = 0;
            for (int e = 0; e < tid; e++) pos += s_lead[e];
            s_pidx[pos] = j;
            s_pgt[pos]  = (int)(unsigned)(best & 0xffffffffu);
        }
        __syncthreads();
        if (tid == 0) {
            int cnt = 0;
            for (int e = 0; e < K; e++) cnt += s_lead[e];
            s_npos = cnt;
            if (m == 0) g_cnt01[s] = cnt;            // blocks 0 and KMAX publish counts
        }
        __syncthreads();

        // block KMAX (stage 1, m==0): cls label correction, overlapped with geometry
        if (bid == KMAX) {
            double part = 0.0;
            if (tid < s_npos) {
                int j   = s_pidx[tid];
                int lab = glab[s_pgt[tid]];
                part = (double)cls[(size_t)j * 16 + 0] - (double)cls[(size_t)j * 16 + lab];
            }
            for (int o = 16; o; o >>= 1) part += __shfl_down_sync(FULLM, part, o);
            if (lane == 0) s_red[w] = part;
            __syncthreads();
            if (tid == 0) {
                double cs = 0.0;
                for (int q = 0; q < NTHR / 32; q++) cs += s_red[q];
                g_corr_val = cs;
            }
        }

        // geometry task (if this block has one)
        if (m < s_npos) {
            const float* rp  = s ? rpr : rpi;
            int j  = s_pidx[m];
            int gi = s_pgt[m];
            const float* g8  = gtb + 8 * gi;
            const float* p18 = rp + (size_t)j * 18;
            if (tid < 4) {
                float2 c = make_float2(g8[2 * tid], g8[2 * tid + 1]);
                sGT[tid] = c;
                sPtsB[tid] = c;
            }
            if (tid >= 4 && tid < 13) {
                float2 c = make_float2(p18[2 * (tid - 4)], p18[2 * (tid - 4) + 1]);
                sP9[tid - 4] = c;
                sPtsB[tid] = c;
            }
            __syncthreads();

            if (w < 13) {
                int h = hull_member_warp(sPtsB, 13, w, lane);
                if (lane == 0) sHb[w] = h;
            } else if (w >= 16 && w < 25) {
                int h = hull_member_warp(sP9, 9, w - 16, lane);
                if (lane == 0) sHa[w - 16] = h;
            } else if (w == 13) {
                if (lane < 4) {
                    float cmx = (sGT[0].x + sGT[1].x + sGT[2].x + sGT[3].x) * 0.25f;
                    float cmy = (sGT[0].y + sGT[1].y + sGT[2].y + sGT[3].y) * 0.25f;
                    sKeyG[lane] = atan2f(__fsub_rn(sGT[lane].y, cmy),
                                         __fsub_rn(sGT[lane].x, cmx));
                }
                __syncwarp();
                if (lane < 4) {
                    float ki = sKeyG[lane];
                    int r = 0;
                    #pragma unroll
                    for (int j2 = 0; j2 < 4; j2++) {
                        float kj = sKeyG[j2];
                        r += (kj < ki) || (kj == ki && j2 < lane);
                    }
                    sG[r] = sGT[lane];
                }
            }
            __syncthreads();

            if (w == 0) {
                int c = hull_finish_warp(sP9, 9, sHa, sKeyA, sVa, lane);
                if (lane == 0) {
                    s_apred = shoelace16(sVa, c);
                    float sgt = 0.f;
                    #pragma unroll
                    for (int i = 0; i < 4; i++) {
                        int nx = (i + 1 < 4) ? i + 1 : 0;
                        sgt = __fadd_rn(sgt, cross_nf(sG[i].x, sG[i].y, sG[nx].x, sG[nx].y));
                    }
                    s_agt = 0.5f * fabsf(sgt);
                }
                for (int e = 0; e < 4; e++) clip_warp(sVa, c, sG[e], sG[(e + 1) & 3], lane, sScrA);
                if (lane == 0) s_aint = shoelace16(sVa, c);
            } else if (w == 1) {
                int ch = hull_finish_warp(sPtsB, 13, sHb, sKeyB, sVb, lane);
                if (lane == 0) s_ahull = shoelace16(sVb, ch);
            } else if (w == 2) {
                float val = 0.f;
                if (lane < 9) {
                    float mx = -f_inf();
                    #pragma unroll
                    for (int e = 0; e < 4; e++) {
                        float ex = __fsub_rn(sG[(e + 1) & 3].x, sG[e].x);
                        float ey = __fsub_rn(sG[(e + 1) & 3].y, sG[e].y);
                        float num = cross_nf(ex, ey, __fsub_rn(sP9[lane].x, sG[e].x),
                                                     __fsub_rn(sP9[lane].y, sG[e].y));
                        float sv = __fdiv_rn(num,
                            __fadd_rn(__fsqrt_rn(__fadd_rn(__fmul_rn(ex, ex),
                                                           __fmul_rn(ey, ey))), 1e-9f));
                        mx = fmaxf(mx, -sv);
                    }
                    val = fmaxf(mx, 0.f);
                }
                float acc = 0.f;
                #pragma unroll
                for (int p = 0; p < 9; p++) {
                    float vp = __shfl_sync(FULLM, val, p);
                    acc = __fadd_rn(acc, vp);
                }
                if (lane == 0) s_oob = __fdiv_rn(acc, 9.0f);
            }
            __syncthreads();

            if (tid == 0) {
                float uni = __fsub_rn(__fadd_rn(s_apred, s_agt), s_aint);
                float iou = __fdiv_rn(s_aint, __fadd_rn(uni, 1e-16f));
                float giou = __fsub_rn(iou, __fdiv_rn(__fsub_rn(s_ahull, uni),
                                                      __fadd_rn(s_ahull, 1e-16f)));
                g_task_gl[s][m]  = (double)__fsub_rn(1.0f, giou);
                g_task_oob[s][m] = (double)s_oob;
            }
        }
    }

    // ---------------- ticket: last block to finish does the final combine ----------------
    __threadfence();
    __syncthreads();
    if (tid == 0) {
        unsigned prev = atomicAdd(&g_ticket, 1u);
        s_last = (prev == NSM - 1) ? 1 : 0;
    }
    __syncthreads();

    if (s_last) {
        int c0 = *(volatile int*)&g_cnt01[0];
        int c1 = *(volatile int*)&g_cnt01[1];
        for (int q = tid; q < 2 * KMAX; q += NTHR) {
            int s2 = q >> 6, mm = q & 63;
            int cs = s2 ? c1 : c0;
            s_tgl[q] = (mm < cs) ? __ldcg(&g_task_gl[s2][mm])  : 0.0;
            s_tob[q] = (mm < cs) ? __ldcg(&g_task_oob[s2][mm]) : 0.0;
        }
        for (int q = tid; q < NSM; q += NTHR) s_lse[q] = __ldcg(&g_blk_lse[q]);
        __syncthreads();
        if (tid == 0) {
            double lse = 0.0;
            for (int q = 0; q < NSM; q++) lse += s_lse[q];         // fixed order
            double loc_i = 0.0, sc_i = 0.0, loc_r = 0.0, sc_r = 0.0;
            for (int mm = 0; mm < KMAX; mm++) { loc_i += s_tgl[mm];        sc_i += s_tob[mm]; }
            for (int mm = 0; mm < KMAX; mm++) { loc_r += s_tgl[KMAX + mm]; sc_r += s_tob[KMAX + mm]; }
            double corr = __ldcg(&g_corr_val);
            double cls_loss = (lse + corr) / (double)N;
            double ni = (double)max(c0, 1);
            double nr = (double)max(c1, 1);
            double loss = cls_loss
                        + 0.3  * (loc_i / ni)
                        + 1.0  * (loc_r / nr)
                        + 0.05 * (sc_i / ni)
                        + 0.1  * (sc_r / nr);
            out[0] = (float)loss;
            g_ticket = 0;                                            // reset for next replay
        }
        // restore zero-init g_best for the next (identical) launch
        for (int q = tid; q < NB; q += NTHR) { g_best[0][q] = 0ull; g_best[1][q] = 0ull; }
    }
}

// ---------------- launch ----------------
extern "C" void kernel_launch(void* const* d_in, const int* in_sizes, int n_in,
                              void* d_out, int out_size)
{
    const float* rpi  = (const float*)d_in[0];
    const float* rpr  = (const float*)d_in[1];
    const float* cls  = (const float*)d_in[2];
    const float* pstr = (const float*)d_in[3];
    const float* gtb  = (const float*)d_in[4];
    const int*   glab = (const int*)d_in[5];
    float* out = (float*)d_out;

    int N = in_sizes[3];          // points_stride element count
    int K = in_sizes[5];          // gt_labels element count (=64)
    if (K > KMAX) K = KMAX;

    k_fused<<<NSM, NTHR>>>(rpi, rpr, cls, pstr, gtb, glab, N, K, out);
}

// round 9
// speedup vs baseline: 6.6708x; 1.0192x over previous
#include <cuda_runtime.h>
#include <math.h>
#include <stdint.h>

#define KMAX 64
#define BUF  16
#define NLVL 5          // levels 3..7
#define NB   (NLVL * KMAX)
#define NSM  148        // <= SM count on GB300 (152): all blocks co-resident
#define NTHR 1024
#define FULLM 0xffffffffu

// ---------------- device-global state (zero-init; restored by the last block) ----------------
__device__ unsigned g_bar_cnt;
__device__ unsigned g_bar_gen;                   // monotonic across launches
__device__ unsigned g_ticket;                    // completion counter (reset each launch)
__device__ unsigned long long g_best[2][NB];     // INVERTED packed keys; 0 = empty (max-reduced)
__device__ int    g_cnt01[2];
__device__ double g_blk_lse[NSM];
__device__ double g_corr_val;
__device__ double g_task_gl[2][KMAX];
__device__ double g_task_oob[2][KMAX];

__device__ __forceinline__ float f_inf() { return __int_as_float(0x7f800000); }

// Non-FMA cross product: matches XLA's unfused mul/sub semantics exactly.
__device__ __forceinline__ float cross_nf(float ax, float ay, float bx, float by)
{
    return __fsub_rn(__fmul_rn(ax, by), __fmul_rn(ay, bx));
}

__device__ __forceinline__ void grid_barrier()
{
    __syncthreads();
    if (threadIdx.x == 0) {
        volatile unsigned* vgen = &g_bar_gen;
        unsigned gen = *vgen;
        __threadfence();
        unsigned prev = atomicAdd(&g_bar_cnt, 1u);
        if (prev == NSM - 1) {
            g_bar_cnt = 0;
            __threadfence();
            atomicAdd(&g_bar_gen, 1u);
        } else {
            while (*vgen == gen) { }
        }
    }
    __syncthreads();
}

// ---------------- geometry helpers (bit-identical to prior passing rounds) ----------------
__device__ float shoelace16(const float2* V, int c)
{
    float s = 0.f;
    #pragma unroll
    for (int i = 0; i < BUF; i++) {
        if (i >= c) continue;
        int nxt = (i + 1 < c) ? i + 1 : 0;
        s = __fadd_rn(s, cross_nf(V[i].x, V[i].y, V[nxt].x, V[nxt].y));
    }
    return 0.5f * fabsf(s);
}

__device__ __forceinline__ int hull_member_warp(const float2* pts, int n, int i, int lane)
{
    bool flag = false;
    if (lane < n && lane != i) {
        float pix = pts[i].x, piy = pts[i].y;
        float dx = __fsub_rn(pts[lane].x, pix), dy = __fsub_rn(pts[lane].y, piy);
        float mn = f_inf();
        for (int k = 0; k < n; k++) {
            float cr = cross_nf(dx, dy, __fsub_rn(pts[k].x, pix), __fsub_rn(pts[k].y, piy));
            mn = fminf(mn, cr);
        }
        flag = (mn >= -1e-6f);
    }
    return __ballot_sync(FULLM, flag) != 0;
}

__device__ int hull_finish_warp(const float2* pts, int n, const int* hflag,
                                float* skey, float2* sV, int lane)
{
    bool hf = (lane < n) ? (hflag[lane] != 0) : false;
    unsigned mask = __ballot_sync(FULLM, hf);
    int cnt = __popc(mask);
    float sx = 0.f, sy = 0.f;
    for (int i = 0; i < n; i++)
        if ((mask >> i) & 1) { sx = __fadd_rn(sx, pts[i].x); sy = __fadd_rn(sy, pts[i].y); }
    float cd = (float)(cnt > 0 ? cnt : 1);
    float cenx = __fdiv_rn(sx, cd), ceny = __fdiv_rn(sy, cd);
    if (lane < n)
        skey[lane] = hf ? atan2f(__fsub_rn(pts[lane].y, ceny), __fsub_rn(pts[lane].x, cenx))
                        : f_inf();
    __syncwarp();
    if (lane < n) {
        float ki = skey[lane];
        int r = 0;
        for (int j = 0; j < n; j++) {
            float kj = skey[j];
            r += (kj < ki) || (kj == ki && j < lane);   // stable rank == argsort
        }
        sV[r] = pts[lane];
    }
    if (lane >= n && lane < BUF) sV[lane] = make_float2(0.f, 0.f);
    __syncwarp();
    return cnt;
}

__device__ void clip_warp(float2* V, int& c, float2 a, float2 b, int lane, float2* scratch)
{
    float ex = __fsub_rn(b.x, a.x), ey = __fsub_rn(b.y, a.y);
    int cc = c;
    bool active = (lane < BUF) && (lane < cc);
    int nxt = (lane + 1 < cc) ? lane + 1 : 0;
    float2 cur = active ? V[lane] : make_float2(0.f, 0.f);
    float2 nx  = active ? V[nxt]  : make_float2(0.f, 0.f);
    float s_cur = cross_nf(ex, ey, __fsub_rn(cur.x, a.x), __fsub_rn(cur.y, a.y));
    float s_nxt = cross_nf(ex, ey, __fsub_rn(nx.x,  a.x), __fsub_rn(nx.y,  a.y));
    bool in_cur = s_cur >= 0.f, in_nxt = s_nxt >= 0.f;
    float den = __fsub_rn(s_cur, s_nxt);
    float t = (fabsf(den) > 1e-9f) ? __fdiv_rn(s_cur, den) : 0.f;
    float2 ipt = make_float2(__fadd_rn(cur.x, __fmul_rn(t, __fsub_rn(nx.x, cur.x))),
                             __fadd_rn(cur.y, __fmul_rn(t, __fsub_rn(nx.y, cur.y))));
    bool f_int = active && (in_cur != in_nxt);
    bool f_nxt = active && in_nxt;
    unsigned bi = __ballot_sync(FULLM, f_int);
    unsigned bn = __ballot_sync(FULLM, f_nxt);
    unsigned below = (1u << lane) - 1u;
    int pos_i = __popc(bi & below) + __popc(bn & below);
    int pos_n = pos_i + (f_int ? 1 : 0);
    int nc = __popc(bi) + __popc(bn);
    __syncwarp();
    if (f_int && pos_i < BUF) scratch[pos_i] = ipt;
    if (f_nxt && pos_n < BUF) scratch[pos_n] = nx;
    __syncwarp();
    if (lane < BUF) V[lane] = (lane < nc) ? scratch[lane] : make_float2(0.f, 0.f);
    __syncwarp();
    c = nc;
}

// ---------------- the one fused kernel ----------------
// (NTHR, 1): 1 block/SM is all the grid uses -> let ptxas have the full 64 regs/thread.
// (Plain __launch_bounds__(1024) made ptxas target 2 blocks/SM and squeeze to 32 regs,
//  spilling v[16]/hull state to local memory — the dominant cost in rounds 7-8.)
__global__ void __launch_bounds__(NTHR, 1) k_fused(
    const float* __restrict__ rpi, const float* __restrict__ rpr,
    const float* __restrict__ cls, const float* __restrict__ pstr,
    const float* __restrict__ gtb, const int* __restrict__ glab,
    int N, int K, float* __restrict__ out)
{
    __shared__ float  s_cx[KMAX], s_cy[KMAX], s_rw[KMAX], s_rh[KMAX];
    __shared__ int    s_lvl[KMAX];
    __shared__ float4 s_bkt[NB];
    __shared__ int    s_k2b[KMAX];
    __shared__ int    s_cnt[NLVL];
    __shared__ unsigned long long sb0[NB], sb1[NB];
    __shared__ double s_red[32];
    // replay (per-block, own stage)
    __shared__ unsigned long long s_cmp[KMAX];
    __shared__ int s_j[KMAX];
    __shared__ int s_lead[KMAX];
    __shared__ int s_pidx[KMAX], s_pgt[KMAX];
    __shared__ int s_npos;
    // geom
    __shared__ float2 sP9[9];
    __shared__ float2 sGT[4];
    __shared__ float2 sG[4];
    __shared__ float2 sPtsB[13];
    __shared__ int    sHa[9], sHb[13];
    __shared__ float2 sVa[BUF], sVb[BUF];
    __shared__ float2 sScrA[BUF];
    __shared__ float  sKeyA[13], sKeyB[13], sKeyG[4];
    __shared__ float  s_apred, s_agt, s_aint, s_ahull, s_oob;
    // final
    __shared__ double s_tgl[2 * KMAX], s_tob[2 * KMAX];
    __shared__ double s_lse[NSM];
    __shared__ int    s_last;

    const int tid  = threadIdx.x;
    const int bid  = blockIdx.x;
    const int lane = tid & 31;
    const int w    = tid >> 5;

    // ---------------- Phase A: prep + assign + lse ----------------
    for (int q = tid; q < NB; q += NTHR) { sb0[q] = 0ull; sb1[q] = 0ull; }
    if (tid < K) {
        const float* r = gtb + 8 * tid;
        float xmn = fminf(fminf(r[0], r[2]), fminf(r[4], r[6]));
        float xmx = fmaxf(fmaxf(r[0], r[2]), fmaxf(r[4], r[6]));
        float ymn = fminf(fminf(r[1], r[3]), fminf(r[5], r[7]));
        float ymx = fmaxf(fmaxf(r[1], r[3]), fmaxf(r[5], r[7]));
        float ww = fmaxf(__fsub_rn(xmx, xmn), 1e-6f);
        float hh = fmaxf(__fsub_rn(ymx, ymn), 1e-6f);
        s_cx[tid] = __fmul_rn(__fadd_rn(xmn, xmx), 0.5f);
        s_cy[tid] = __fmul_rn(__fadd_rn(ymn, ymx), 0.5f);
        s_rw[tid] = __fdiv_rn(1.0f, ww);
        s_rh[tid] = __fdiv_rn(1.0f, hh);
        float lv = __fmul_rn(__fadd_rn(log2f(__fdiv_rn(ww, 4.0f)),
                                       log2f(__fdiv_rn(hh, 4.0f))), 0.5f);
        int lvl = (int)lv;
        s_lvl[tid] = max(3, min(7, lvl));
    }
    __syncthreads();
    if (tid == 0) {                                  // serial bucket build, ascending k
        int cnt[NLVL];
        #pragma unroll
        for (int l = 0; l < NLVL; l++) cnt[l] = 0;
        for (int q = 0; q < K; q++) {
            int li = s_lvl[q] - 3;
            int slot = li * KMAX + cnt[li];
            s_bkt[slot] = make_float4(s_cx[q], s_cy[q], s_rw[q], s_rh[q]);
            s_k2b[q] = slot;
            cnt[li]++;
        }
        #pragma unroll
        for (int l = 0; l < NLVL; l++) s_cnt[l] = cnt[l];
    }
    __syncthreads();

    double lterm = 0.0;
    for (int n = bid * NTHR + tid; n - tid < N; n += NSM * NTHR) {
        bool act = (n < N);
        int li = 0;
        float2 pi = make_float2(0.f, 0.f), pr = make_float2(0.f, 0.f);
        if (act) {
            li = (31 - __clz((int)pstr[n])) - 3;
            pi = __ldg((const float2*)(rpi + (size_t)n * 18 + 8));
            pr = __ldg((const float2*)(rpr + (size_t)n * 18 + 8));
        }
        unsigned un = (unsigned)n;
        unsigned actmask = __ballot_sync(FULLM, act);
        if (actmask) {
            int src = __ffs(actmask) - 1;
            int uli = __shfl_sync(FULLM, li, src);
            bool uniform = __all_sync(FULLM, !act || (li == uli));
            if (uniform) {
                int cnt = s_cnt[uli], base = uli * KMAX;
                for (int m = 0; m < cnt; m++) {
                    int slot = base + m;
                    float4 gq = s_bkt[slot];
                    unsigned long long ki = 0ull, kr = 0ull;
                    if (act) {
                        float dxi = __fmul_rn(__fsub_rn(pi.x, gq.x), gq.z);
                        float dyi = __fmul_rn(__fsub_rn(pi.y, gq.y), gq.w);
                        float ddi = __fadd_rn(__fmul_rn(dxi, dxi), __fmul_rn(dyi, dyi));
                        ki = ~(((unsigned long long)__float_as_uint(ddi) << 32) | un);
                        float dxr = __fmul_rn(__fsub_rn(pr.x, gq.x), gq.z);
                        float dyr = __fmul_rn(__fsub_rn(pr.y, gq.y), gq.w);
                        float ddr = __fadd_rn(__fmul_rn(dxr, dxr), __fmul_rn(dyr, dyr));
                        kr = ~(((unsigned long long)__float_as_uint(ddr) << 32) | un);
                    }
                    #pragma unroll
                    for (int o = 16; o; o >>= 1) {
                        unsigned long long ti = __shfl_down_sync(FULLM, ki, o);
                        unsigned long long tr = __shfl_down_sync(FULLM, kr, o);
                        if (ti > ki) ki = ti;
                        if (tr > kr) kr = tr;
                    }
                    if (lane == 0) {
                        if (ki > sb0[slot]) atomicMax(&sb0[slot], ki);
                        if (kr > sb1[slot]) atomicMax(&sb1[slot], kr);
                    }
                }
            } else if (act) {
                int cnt = s_cnt[li], base = li * KMAX;
                for (int m = 0; m < cnt; m++) {
                    int slot = base + m;
                    float4 gq = s_bkt[slot];
                    float dxi = __fmul_rn(__fsub_rn(pi.x, gq.x), gq.z);
                    float dyi = __fmul_rn(__fsub_rn(pi.y, gq.y), gq.w);
                    float ddi = __fadd_rn(__fmul_rn(dxi, dxi), __fmul_rn(dyi, dyi));
                    unsigned long long ki = ~(((unsigned long long)__float_as_uint(ddi) << 32) | un);
                    if (ki > sb0[slot]) atomicMax(&sb0[slot], ki);
                    float dxr = __fmul_rn(__fsub_rn(pr.x, gq.x), gq.z);
                    float dyr = __fmul_rn(__fsub_rn(pr.y, gq.y), gq.w);
                    float ddr = __fadd_rn(__fmul_rn(dxr, dxr), __fmul_rn(dyr, dyr));
                    unsigned long long kr = ~(((unsigned long long)__float_as_uint(ddr) << 32) | un);
                    if (kr > sb1[slot]) atomicMax(&sb1[slot], kr);
                }
            }
        }
        if (act) {
            const float4* c4 = (const float4*)(cls + (size_t)n * 16);
            float v[16];
            #pragma unroll
            for (int j = 0; j < 4; j++) {
                float4 f = __ldg(c4 + j);
                v[4 * j] = f.x; v[4 * j + 1] = f.y; v[4 * j + 2] = f.z; v[4 * j + 3] = f.w;
            }
            float mm = v[0];
            #pragma unroll
            for (int j = 1; j < 16; j++) mm = fmaxf(mm, v[j]);
            float ss = 0.f;
            #pragma unroll
            for (int j = 0; j < 16; j++) ss += __expf(v[j] - mm);
            lterm += (double)((mm + __logf(ss)) - v[0]);
        }
    }
    for (int o = 16; o; o >>= 1) lterm += __shfl_down_sync(FULLM, lterm, o);
    if (lane == 0) s_red[w] = lterm;
    __syncthreads();
    if (tid == 0) {
        double bs = 0.0;
        for (int q = 0; q < NTHR / 32; q++) bs += s_red[q];
        g_blk_lse[bid] = bs;
    }
    for (int q = tid; q < NB; q += NTHR) {
        if (sb0[q]) atomicMax(&g_best[0][q], sb0[q]);
        if (sb1[q]) atomicMax(&g_best[1][q], sb1[q]);
    }

    grid_barrier();   // --- the ONLY grid barrier: assign complete ---

    // ---------------- Phase B+C (blocks 0..127): per-block replay of OWN stage + task ----------------
    if (bid < 2 * KMAX) {
        int s = (bid >= KMAX) ? 1 : 0;
        int m = bid - s * KMAX;

        if (tid < KMAX) {
            unsigned long long v = (tid < K) ? __ldcg(&g_best[s][s_k2b[tid]]) : 0ull;
            bool valid = (v != 0ull);
            unsigned long long pk = ~v;              // (md_bits<<32)|point_idx
            s_j[tid]   = valid ? (int)(unsigned)(pk & 0xffffffffu) : (-1 - tid);
            s_cmp[tid] = valid ? (((pk >> 32) << 32) | (unsigned)tid) : ~0ull;
        }
        __syncthreads();
        if (tid < KMAX) {
            int j = s_j[tid];
            bool lead = (j >= 0);
            if (lead)
                for (int e = 0; e < tid; e++)
                    if (s_j[e] == j) { lead = false; break; }
            s_lead[tid] = lead ? 1 : 0;
        }
        __syncthreads();
        if (tid < K && s_lead[tid]) {
            int j = s_j[tid];
            unsigned long long best = s_cmp[tid];
            for (int e = 0; e < K; e++)
                if (s_j[e] == j && s_cmp[e] < best) best = s_cmp[e];
            int pos = 0;
            for (int e = 0; e < tid; e++) pos += s_lead[e];
            s_pidx[pos] = j;
            s_pgt[pos]  = (int)(unsigned)(best & 0xffffffffu);
        }
        __syncthreads();
        if (tid == 0) {
            int cnt = 0;
            for (int e = 0; e < K; e++) cnt += s_lead[e];
            s_npos = cnt;
            if (m == 0) g_cnt01[s] = cnt;            // blocks 0 and KMAX publish counts
        }
        __syncthreads();

        if (bid == KMAX) {
            double part = 0.0;
            if (tid < s_npos) {
                int j   = s_pidx[tid];
                int lab = glab[s_pgt[tid]];
                part = (double)cls[(size_t)j * 16 + 0] - (double)cls[(size_t)j * 16 + lab];
            }
            for (int o = 16; o; o >>= 1) part += __shfl_down_sync(FULLM, part, o);
            if (lane == 0) s_red[w] = part;
            __syncthreads();
            if (tid == 0) {
                double cs = 0.0;
                for (int q = 0; q < NTHR / 32; q++) cs += s_red[q];
                g_corr_val = cs;
            }
        }

        if (m < s_npos) {
            const float* rp  = s ? rpr : rpi;
            int j  = s_pidx[m];
            int gi = s_pgt[m];
            const float* g8  = gtb + 8 * gi;
            const float* p18 = rp + (size_t)j * 18;
            if (tid < 4) {
                float2 c = make_float2(g8[2 * tid], g8[2 * tid + 1]);
                sGT[tid] = c;
                sPtsB[tid] = c;
            }
            if (tid >= 4 && tid < 13) {
                float2 c = make_float2(p18[2 * (tid - 4)], p18[2 * (tid - 4) + 1]);
                sP9[tid - 4] = c;
                sPtsB[tid] = c;
            }
            __syncthreads();

            if (w < 13) {
                int h = hull_member_warp(sPtsB, 13, w, lane);
                if (lane == 0) sHb[w] = h;
            } else if (w >= 16 && w < 25) {
                int h = hull_member_warp(sP9, 9, w - 16, lane);
                if (lane == 0) sHa[w - 16] = h;
            } else if (w == 13) {
                if (lane < 4) {
                    float cmx = (sGT[0].x + sGT[1].x + sGT[2].x + sGT[3].x) * 0.25f;
                    float cmy = (sGT[0].y + sGT[1].y + sGT[2].y + sGT[3].y) * 0.25f;
                    sKeyG[lane] = atan2f(__fsub_rn(sGT[lane].y, cmy),
                                         __fsub_rn(sGT[lane].x, cmx));
                }
                __syncwarp();
                if (lane < 4) {
                    float ki = sKeyG[lane];
                    int r = 0;
                    #pragma unroll
                    for (int j2 = 0; j2 < 4; j2++) {
                        float kj = sKeyG[j2];
                        r += (kj < ki) || (kj == ki && j2 < lane);
                    }
                    sG[r] = sGT[lane];
                }
            }
            __syncthreads();

            if (w == 0) {
                int c = hull_finish_warp(sP9, 9, sHa, sKeyA, sVa, lane);
                if (lane == 0) {
                    s_apred = shoelace16(sVa, c);
                    float sgt = 0.f;
                    #pragma unroll
                    for (int i = 0; i < 4; i++) {
                        int nx = (i + 1 < 4) ? i + 1 : 0;
                        sgt = __fadd_rn(sgt, cross_nf(sG[i].x, sG[i].y, sG[nx].x, sG[nx].y));
                    }
                    s_agt = 0.5f * fabsf(sgt);
                }
                for (int e = 0; e < 4; e++) clip_warp(sVa, c, sG[e], sG[(e + 1) & 3], lane, sScrA);
                if (lane == 0) s_aint = shoelace16(sVa, c);
            } else if (w == 1) {
                int ch = hull_finish_warp(sPtsB, 13, sHb, sKeyB, sVb, lane);
                if (lane == 0) s_ahull = shoelace16(sVb, ch);
            } else if (w == 2) {
                float val = 0.f;
                if (lane < 9) {
                    float mx = -f_inf();
                    #pragma unroll
                    for (int e = 0; e < 4; e++) {
                        float ex = __fsub_rn(sG[(e + 1) & 3].x, sG[e].x);
                        float ey = __fsub_rn(sG[(e + 1) & 3].y, sG[e].y);
                        float num = cross_nf(ex, ey, __fsub_rn(sP9[lane].x, sG[e].x),
                                                     __fsub_rn(sP9[lane].y, sG[e].y));
                        float sv = __fdiv_rn(num,
                            __fadd_rn(__fsqrt_rn(__fadd_rn(__fmul_rn(ex, ex),
                                                           __fmul_rn(ey, ey))), 1e-9f));
                        mx = fmaxf(mx, -sv);
                    }
                    val = fmaxf(mx, 0.f);
                }
                float acc = 0.f;
                #pragma unroll
                for (int p = 0; p < 9; p++) {
                    float vp = __shfl_sync(FULLM, val, p);
                    acc = __fadd_rn(acc, vp);
                }
                if (lane == 0) s_oob = __fdiv_rn(acc, 9.0f);
            }
            __syncthreads();

            if (tid == 0) {
                float uni = __fsub_rn(__fadd_rn(s_apred, s_agt), s_aint);
                float iou = __fdiv_rn(s_aint, __fadd_rn(uni, 1e-16f));
                float giou = __fsub_rn(iou, __fdiv_rn(__fsub_rn(s_ahull, uni),
                                                      __fadd_rn(s_ahull, 1e-16f)));
                g_task_gl[s][m]  = (double)__fsub_rn(1.0f, giou);
                g_task_oob[s][m] = (double)s_oob;
            }
        }
    }

    // ---------------- ticket: last block to finish does the final combine ----------------
    __threadfence();
    __syncthreads();
    if (tid == 0) {
        unsigned prev = atomicAdd(&g_ticket, 1u);
        s_last = (prev == NSM - 1) ? 1 : 0;
    }
    __syncthreads();

    if (s_last) {
        int c0 = *(volatile int*)&g_cnt01[0];
        int c1 = *(volatile int*)&g_cnt01[1];
        for (int q = tid; q < 2 * KMAX; q += NTHR) {
            int s2 = q >> 6, mm = q & 63;
            int cs = s2 ? c1 : c0;
            s_tgl[q] = (mm < cs) ? __ldcg(&g_task_gl[s2][mm])  : 0.0;
            s_tob[q] = (mm < cs) ? __ldcg(&g_task_oob[s2][mm]) : 0.0;
        }
        for (int q = tid; q < NSM; q += NTHR) s_lse[q] = __ldcg(&g_blk_lse[q]);
        __syncthreads();
        if (tid == 0) {
            double lse = 0.0;
            for (int q = 0; q < NSM; q++) lse += s_lse[q];         // fixed order
            double loc_i = 0.0, sc_i = 0.0, loc_r = 0.0, sc_r = 0.0;
            for (int mm = 0; mm < KMAX; mm++) { loc_i += s_tgl[mm];        sc_i += s_tob[mm]; }
            for (int mm = 0; mm < KMAX; mm++) { loc_r += s_tgl[KMAX + mm]; sc_r += s_tob[KMAX + mm]; }
            double corr = __ldcg(&g_corr_val);
            double cls_loss = (lse + corr) / (double)N;
            double ni = (double)max(c0, 1);
            double nr = (double)max(c1, 1);
            double loss = cls_loss
                        + 0.3  * (loc_i / ni)
                        + 1.0  * (loc_r / nr)
                        + 0.05 * (sc_i / ni)
                        + 0.1  * (sc_r / nr);
            out[0] = (float)loss;
            g_ticket = 0;                                            // reset for next replay
        }
        for (int q = tid; q < NB; q += NTHR) { g_best[0][q] = 0ull; g_best[1][q] = 0ull; }
    }
}

// ---------------- launch ----------------
extern "C" void kernel_launch(void* const* d_in, const int* in_sizes, int n_in,
                              void* d_out, int out_size)
{
    const float* rpi  = (const float*)d_in[0];
    const float* rpr  = (const float*)d_in[1];
    const float* cls  = (const float*)d_in[2];
    const float* pstr = (const float*)d_in[3];
    const float* gtb  = (const float*)d_in[4];
    const int*   glab = (const int*)d_in[5];
    float* out = (float*)d_out;

    int N = in_sizes[3];          // points_stride element count
    int K = in_sizes[5];          // gt_labels element count (=64)
    if (K > KMAX) K = KMAX;

    k_fused<<<NSM, NTHR>>>(rpi, rpr, cls, pstr, gtb, glab, N, K, out);
}